// round 13
// baseline (speedup 1.0000x reference)
#include <cuda_runtime.h>
#include <cstdint>

#define N_MAX   50000
#define HDIM    256
#define E_MAX   800000
#define MAXCTX  8

// ---------------------------------------------------------------------------
// Scratch (device globals -- no allocation allowed in kernel_launch)
// ---------------------------------------------------------------------------
__device__ float g_h[N_MAX * HDIM];     // h' = (A @ W) * inv[row]
__device__ float g_agg[N_MAX * HDIM];   // scatter accumulator
__device__ float g_feat[N_MAX * HDIM];  // layer output (feat1 then feat2)
__device__ float g_inv[N_MAX];          // deg, then rsqrt(deg)
__device__ int   g_bcnt[MAXCTX];        // bucket counts (clen in 0..7)
__device__ int   g_boff[MAXCTX];        // bucket offsets (mutated by scatter)
__device__ int   g_perm[N_MAX];         // rows sorted by context_len

// ---------------------------------------------------------------------------
// Degree / normalization
// ---------------------------------------------------------------------------
__global__ void deg_init_kernel(float* deg, int n) {
    int i = blockIdx.x * blockDim.x + threadIdx.x;
    if (i < n) deg[i] = 1.0f;  // self loop
}

__global__ void deg_count_kernel(const int* __restrict__ dst, float* deg, int e) {
    int i = blockIdx.x * blockDim.x + threadIdx.x;
    if (i < e) atomicAdd(&deg[dst[i]], 1.0f);
}

__global__ void inv_sqrt_kernel(float* deg, int n) {
    int i = blockIdx.x * blockDim.x + threadIdx.x;
    if (i < n) deg[i] = rsqrtf(deg[i]);
}

// ---------------------------------------------------------------------------
// Bucket sort of rows by context_len (8 bins) — validated R10
// ---------------------------------------------------------------------------
__global__ void bucket_init_kernel() {
    if (threadIdx.x < MAXCTX) g_bcnt[threadIdx.x] = 0;
}
__global__ void bucket_hist_kernel(const int* __restrict__ clen, int n) {
    int i = blockIdx.x * blockDim.x + threadIdx.x;
    if (i < n) atomicAdd(&g_bcnt[clen[i]], 1);
}
__global__ void bucket_scan_kernel() {
    if (threadIdx.x == 0) {
        int acc = 0;
        for (int b = 0; b < MAXCTX; ++b) { g_boff[b] = acc; acc += g_bcnt[b]; }
    }
}
__global__ void bucket_scatter_kernel(const int* __restrict__ clen, int n) {
    int i = blockIdx.x * blockDim.x + threadIdx.x;
    if (i < n) {
        int p = atomicAdd(&g_boff[clen[i]], 1);
        g_perm[p] = i;
    }
}

// ---------------------------------------------------------------------------
// SGEMM (fp32 SIMT, at FFMA roofline): hprime = (A@W)*inv; agg = hprime
// BM=128, BN=128, BK=16, 256 threads, 8x8 per thread
// ---------------------------------------------------------------------------
__global__ __launch_bounds__(256) void sgemm_fused_kernel(
    const float* __restrict__ A, const float* __restrict__ B,
    const float* __restrict__ inv,
    float* __restrict__ hprime, float* __restrict__ agg, int M)
{
    const int K = 256;
    __shared__ float As[16][128];   // transposed: As[k][m]
    __shared__ float Bs[16][128];

    const int block_row = blockIdx.x * 128;
    const int block_col = blockIdx.y * 128;
    const int tid = threadIdx.x;
    const int tr = tid >> 4;
    const int tc = tid & 15;

    const int a_row0 = tid >> 2;
    const int a_col  = (tid & 3) * 4;
    const int b_row0 = tid >> 5;
    const int b_col  = (tid & 31) * 4;

    float acc[8][8] = {};

    for (int k0 = 0; k0 < K; k0 += 16) {
        #pragma unroll
        for (int it = 0; it < 2; ++it) {
            int m = a_row0 + it * 64;
            int gr = block_row + m;
            float4 v = make_float4(0.f, 0.f, 0.f, 0.f);
            if (gr < M) v = *(const float4*)(A + (size_t)gr * K + k0 + a_col);
            As[a_col + 0][m] = v.x;
            As[a_col + 1][m] = v.y;
            As[a_col + 2][m] = v.z;
            As[a_col + 3][m] = v.w;
        }
        #pragma unroll
        for (int it = 0; it < 2; ++it) {
            int kk = b_row0 + it * 8;
            *(float4*)&Bs[kk][b_col] =
                *(const float4*)(B + (size_t)(k0 + kk) * 256 + block_col + b_col);
        }
        __syncthreads();

        #pragma unroll
        for (int kk = 0; kk < 16; ++kk) {
            float4 a0 = *(const float4*)&As[kk][tr * 8];
            float4 a1 = *(const float4*)&As[kk][tr * 8 + 4];
            float4 b0 = *(const float4*)&Bs[kk][tc * 8];
            float4 b1 = *(const float4*)&Bs[kk][tc * 8 + 4];
            float ar[8] = {a0.x, a0.y, a0.z, a0.w, a1.x, a1.y, a1.z, a1.w};
            float br[8] = {b0.x, b0.y, b0.z, b0.w, b1.x, b1.y, b1.z, b1.w};
            #pragma unroll
            for (int i = 0; i < 8; ++i)
                #pragma unroll
                for (int j = 0; j < 8; ++j)
                    acc[i][j] += ar[i] * br[j];
        }
        __syncthreads();
    }

    #pragma unroll
    for (int i = 0; i < 8; ++i) {
        int gr = block_row + tr * 8 + i;
        if (gr < M) {
            float iv = inv[gr];
            #pragma unroll
            for (int j = 0; j < 8; j += 4) {
                float4 o = make_float4(acc[i][j] * iv, acc[i][j+1] * iv,
                                       acc[i][j+2] * iv, acc[i][j+3] * iv);
                size_t off = (size_t)gr * 256 + block_col + tc * 8 + j;
                *(float4*)(hprime + off) = o;
                *(float4*)(agg    + off) = o;
            }
        }
    }
}

// ---------------------------------------------------------------------------
// Edge scatter: agg[dst,:] += hprime[src,:]   (pure vectorized reductions)
// ---------------------------------------------------------------------------
__global__ void scatter_kernel(const float* __restrict__ hp,
                               const int* __restrict__ src,
                               const int* __restrict__ dst,
                               float* __restrict__ agg, int e)
{
    int warp = (blockIdx.x * blockDim.x + threadIdx.x) >> 5;
    int lane = threadIdx.x & 31;
    if (warp >= e) return;
    int s = __ldg(&src[warp]);
    int d = __ldg(&dst[warp]);
    const float4* hpp = (const float4*)(hp + (size_t)s * 256);
    float* ap = agg + (size_t)d * 256;
    #pragma unroll
    for (int it = 0; it < 2; ++it) {
        int idx = lane + it * 32;
        float4 v = hpp[idx];
        asm volatile("red.global.add.v4.f32 [%0], {%1, %2, %3, %4};"
                     :: "l"(ap + (size_t)idx * 4),
                        "f"(v.x), "f"(v.y), "f"(v.z), "f"(v.w)
                     : "memory");
    }
}

// ---------------------------------------------------------------------------
// Epilogue: feat = agg * inv[row] + b, optional relu
// ---------------------------------------------------------------------------
template <bool RELU>
__global__ void epilogue_kernel(const float* __restrict__ agg,
                                const float* __restrict__ inv,
                                const float* __restrict__ b,
                                float* __restrict__ feat, int total4)
{
    int t = blockIdx.x * blockDim.x + threadIdx.x;
    if (t >= total4) return;
    int row = t >> 6;
    int c4  = t & 63;
    float iv = inv[row];
    float4 v  = ((const float4*)agg)[t];
    float4 bb = ((const float4*)b)[c4];
    v.x = v.x * iv + bb.x; v.y = v.y * iv + bb.y;
    v.z = v.z * iv + bb.z; v.w = v.w * iv + bb.w;
    if (RELU) {
        v.x = fmaxf(v.x, 0.f); v.y = fmaxf(v.y, 0.f);
        v.z = fmaxf(v.z, 0.f); v.w = fmaxf(v.w, 0.f);
    }
    ((float4*)feat)[t] = v;
}

// ---------------------------------------------------------------------------
// TF32 helpers
// ---------------------------------------------------------------------------
__device__ __forceinline__ uint32_t f2tf(float x) {
    uint32_t r;
    asm("cvt.rna.tf32.f32 %0, %1;" : "=r"(r) : "f"(x));
    return r;
}

__device__ __forceinline__ void mma_tf32(float d[4], const uint32_t a[4],
                                         const uint32_t b[2]) {
    asm volatile(
        "mma.sync.aligned.m16n8k8.row.col.f32.tf32.tf32.f32 "
        "{%0,%1,%2,%3}, {%4,%5,%6,%7}, {%8,%9}, {%0,%1,%2,%3};"
        : "+f"(d[0]), "+f"(d[1]), "+f"(d[2]), "+f"(d[3])
        : "r"(a[0]), "r"(a[1]), "r"(a[2]), "r"(a[3]),
          "r"(b[0]), "r"(b[1]));
}

// Fragment-layout smem (numerically validated R9/R10), KS=4 k-steps (BK=32):
//  A word = ((mt*4+ks)*32 + (r&7)*4 + (kk&3))*4 + (kk>>2)*2 + (r>>3)
//     (mt=m>>4, r=m&15, ks=k>>3, kk=k&7); fragment = one LDS.128 at
//     ((mt*4+ks)*32 + lane)*4, conflict-free.
//  B word = (((nt*4+ks)*4 + (kk&3))*8 + (n&7))*2 + (kk>>2)   (nt=n>>3);
//     fragment = one LDS.64 at ((((nt*4+ks)*4+tig)*8+g)*2.
#define A_WORDS 4096   // 128 m x 32 k
#define B_WORDS 4096   // 32 k x 128 n

// ---------------------------------------------------------------------------
// Context GEMM, TF32 TC, fragment-layout smem, DOUBLE-BUFFERED stages,
// bucketed rows, fused final product:
//   out[row,c] = feat2[row,c] * ( sum_{j<len[row]} feat2[label[row,j],:]
//                                 @ Wr[j*256:, c]  + rb[c] )
// BM=128, BN=128, BK=32, 8 warps (2x4), warp tile 64x32 via m16n8k8.
// One __syncthreads per K-iteration.
// ---------------------------------------------------------------------------
__global__ __launch_bounds__(256, 1) void ctx_gemm_tc_kernel(
    const float* __restrict__ feat,
    const int* __restrict__ perm,      // [M] rows sorted by clen
    const int* __restrict__ label,     // [M, 8]
    const int* __restrict__ clen,      // [M]
    const float* __restrict__ Wr,      // [2048, 256]
    const float* __restrict__ rb,      // [256]
    float* __restrict__ out, int M)
{
    __shared__ uint32_t As[2][A_WORDS];
    __shared__ uint32_t Bs[2][B_WORDS];
    __shared__ int s_label[128][MAXCTX];
    __shared__ int s_len[128];
    __shared__ int s_row[128];
    __shared__ int s_maxlen;

    const int brow = blockIdx.x * 128;
    const int bcol = blockIdx.y * 128;
    const int tid  = threadIdx.x;
    const int lane = tid & 31;
    const int warp = tid >> 5;
    const int g    = lane >> 2;   // 0..7
    const int tig  = lane & 3;    // 0..3
    const int wm   = warp & 1;    // warp row (2)
    const int wn   = warp >> 1;   // warp col (4)

    // --- stage per-row metadata through the permutation ---
    if (tid < 128) {
        int gi = brow + tid;
        int row = (gi < M) ? perm[gi] : -1;
        s_row[tid] = row;
        s_len[tid] = (row >= 0) ? clen[row] : 0;
    }
    __syncthreads();
    for (int i = tid; i < 128 * MAXCTX; i += 256) {
        int r = i >> 3, j = i & 7;
        int row = s_row[r];
        s_label[r][j] = (row >= 0) ? label[(size_t)row * MAXCTX + j] : 0;
    }
    if (warp == 0) {
        int v = max(max(s_len[lane], s_len[lane + 32]),
                    max(s_len[lane + 64], s_len[lane + 96]));
        #pragma unroll
        for (int o = 16; o; o >>= 1) v = max(v, __shfl_xor_sync(0xffffffffu, v, o));
        if (lane == 0) s_maxlen = v;
    }
    __syncthreads();
    const int K_eff = s_maxlen * 256;   // bucketed: ~= len(bucket)*256

    float acc[4][4][4];
    #pragma unroll
    for (int i = 0; i < 4; ++i)
        #pragma unroll
        for (int j = 0; j < 4; ++j)
            #pragma unroll
            for (int c = 0; c < 4; ++c) acc[i][j][c] = 0.f;

    // loader indices
    const int lm  = tid >> 1;          // A row 0..127
    const int lkb = (tid & 1) * 16;    // A k-base 0 / 16
    const int bkk = tid & 31;          // B k-row 0..31
    const int bnb = (tid >> 5) * 16;   // B n-base

    float4 rA[4], rB[4];

    auto loadTiles = [&](int k0) {
        const int j   = k0 >> 8;            // context slot (constant in a tile)
        const int kc0 = (k0 & 255) + lkb;
        const int L   = s_len[lm];
        const float* abase = feat + (size_t)s_label[lm][j] * HDIM + kc0;
        #pragma unroll
        for (int it = 0; it < 4; ++it) {
            float4 v = make_float4(0.f, 0.f, 0.f, 0.f);
            if (j < L) v = *(const float4*)(abase + it * 4);
            rA[it] = v;
        }
        const float* bbase = Wr + (size_t)(k0 + bkk) * HDIM + bcol + bnb;
        #pragma unroll
        for (int it = 0; it < 4; ++it)
            rB[it] = *(const float4*)(bbase + it * 4);
    };

    auto storeTiles = [&](int st) {
        float av[16] = {rA[0].x, rA[0].y, rA[0].z, rA[0].w,
                        rA[1].x, rA[1].y, rA[1].z, rA[1].w,
                        rA[2].x, rA[2].y, rA[2].z, rA[2].w,
                        rA[3].x, rA[3].y, rA[3].z, rA[3].w};
        const int mt = lm >> 4, r = lm & 15;
        #pragma unroll
        for (int o = 0; o < 16; ++o) {
            int k = lkb + o, ks = k >> 3, kk = k & 7;
            int w = ((mt * 4 + ks) * 32 + (r & 7) * 4 + (kk & 3)) * 4
                    + (kk >> 2) * 2 + (r >> 3);
            As[st][w] = f2tf(av[o]);
        }
        float bv[16] = {rB[0].x, rB[0].y, rB[0].z, rB[0].w,
                        rB[1].x, rB[1].y, rB[1].z, rB[1].w,
                        rB[2].x, rB[2].y, rB[2].z, rB[2].w,
                        rB[3].x, rB[3].y, rB[3].z, rB[3].w};
        const int ks = bkk >> 3, kk = bkk & 7, t4 = kk & 3, h = kk >> 2;
        #pragma unroll
        for (int o = 0; o < 16; ++o) {
            int n = bnb + o, nt = n >> 3, g2 = n & 7;
            int w = (((nt * 4 + ks) * 4 + t4) * 8 + g2) * 2 + h;
            Bs[st][w] = f2tf(bv[o]);
        }
    };

    if (K_eff > 0) {
        loadTiles(0);
        storeTiles(0);
        __syncthreads();

        int st = 0;
        for (int k0 = 0; k0 < K_eff; k0 += 32) {
            bool more = (k0 + 32) < K_eff;
            if (more) loadTiles(k0 + 32);   // global prefetch, hidden under MMAs

            const uint32_t* as = As[st];
            const uint32_t* bs = Bs[st];
            #pragma unroll
            for (int ks = 0; ks < 4; ++ks) {
                uint32_t af[4][4], bf[4][2];
                #pragma unroll
                for (int i = 0; i < 4; ++i) {
                    int base = (((wm * 4 + i) * 4 + ks) * 32 + lane) * 4;
                    uint4 a4 = *(const uint4*)(as + base);
                    af[i][0] = a4.x; af[i][1] = a4.y; af[i][2] = a4.z; af[i][3] = a4.w;
                }
                #pragma unroll
                for (int jn = 0; jn < 4; ++jn) {
                    int base = ((((wn * 4 + jn) * 4 + ks) * 4 + tig) * 8 + g) * 2;
                    uint2 b2 = *(const uint2*)(bs + base);
                    bf[jn][0] = b2.x; bf[jn][1] = b2.y;
                }
                #pragma unroll
                for (int i = 0; i < 4; ++i)
                    #pragma unroll
                    for (int jn = 0; jn < 4; ++jn)
                        mma_tf32(acc[i][jn], af[i], bf[jn]);
            }
            if (more) {
                storeTiles(st ^ 1);     // write the other stage; no reader yet
                __syncthreads();        // single barrier per K-iteration
                st ^= 1;
            }
        }
    }

    // fused epilogue through permutation: out[row] = feat2[row] * (acc + rb)
    #pragma unroll
    for (int i = 0; i < 4; ++i) {
        int lr0 = wm * 64 + i * 16 + g;
        int lr1 = lr0 + 8;
        int row0 = s_row[lr0];
        int row1 = s_row[lr1];
        #pragma unroll
        for (int jn = 0; jn < 4; ++jn) {
            int c = bcol + wn * 32 + jn * 8 + tig * 2;
            float2 bv = *(const float2*)(rb + c);
            if (row0 >= 0) {
                float2 fv = *(const float2*)(feat + (size_t)row0 * HDIM + c);
                float2 o;
                o.x = (acc[i][jn][0] + bv.x) * fv.x;
                o.y = (acc[i][jn][1] + bv.y) * fv.y;
                *(float2*)(out + (size_t)row0 * HDIM + c) = o;
            }
            if (row1 >= 0) {
                float2 fv = *(const float2*)(feat + (size_t)row1 * HDIM + c);
                float2 o;
                o.x = (acc[i][jn][2] + bv.x) * fv.x;
                o.y = (acc[i][jn][3] + bv.y) * fv.y;
                *(float2*)(out + (size_t)row1 * HDIM + c) = o;
            }
        }
    }
}

// ---------------------------------------------------------------------------
// Launch
// ---------------------------------------------------------------------------
extern "C" void kernel_launch(void* const* d_in, const int* in_sizes, int n_in,
                              void* d_out, int out_size)
{
    const float* x     = (const float*)d_in[0];
    const int*   ei    = (const int*)  d_in[1];   // [2, E]: src row then dst row
    const int*   label = (const int*)  d_in[2];
    const int*   clen  = (const int*)  d_in[3];
    const float* gW    = (const float*)d_in[4];
    const float* gb    = (const float*)d_in[5];
    const float* rW    = (const float*)d_in[6];
    const float* rb    = (const float*)d_in[7];
    float*       out   = (float*)d_out;

    const int N = in_sizes[3];
    const int E = in_sizes[1] / 2;
    const int* src = ei;
    const int* dst = ei + E;

    float *hp, *agg, *feat, *inv;
    int *perm;
    cudaGetSymbolAddress((void**)&hp,   g_h);
    cudaGetSymbolAddress((void**)&agg,  g_agg);
    cudaGetSymbolAddress((void**)&feat, g_feat);
    cudaGetSymbolAddress((void**)&inv,  g_inv);
    cudaGetSymbolAddress((void**)&perm, g_perm);

    const int total4 = N * (HDIM / 4);
    const int TPB = 256;
    dim3 gemm_grid((N + 127) / 128, 2);   // BN=128 -> 2 column blocks

    // --- normalization + length bucketing ---
    deg_init_kernel<<<(N + TPB - 1) / TPB, TPB>>>(inv, N);
    deg_count_kernel<<<(E + TPB - 1) / TPB, TPB>>>(dst, inv, E);
    inv_sqrt_kernel<<<(N + TPB - 1) / TPB, TPB>>>(inv, N);
    bucket_init_kernel<<<1, 32>>>();
    bucket_hist_kernel<<<(N + TPB - 1) / TPB, TPB>>>(clen, N);
    bucket_scan_kernel<<<1, 1>>>();
    bucket_scatter_kernel<<<(N + TPB - 1) / TPB, TPB>>>(clen, N);

    // --- GCN layer 1: feat1 = relu(inv*scatter(h') + b), h' = (x@W)*inv ---
    sgemm_fused_kernel<<<gemm_grid, TPB>>>(x, gW, inv, hp, agg, N);
    scatter_kernel<<<(E * 32 + TPB - 1) / TPB, TPB>>>(hp, src, dst, agg, E);
    epilogue_kernel<true><<<(total4 + TPB - 1) / TPB, TPB>>>(agg, inv, gb, feat, total4);

    // --- GCN layer 2 ---
    sgemm_fused_kernel<<<gemm_grid, TPB>>>(feat, gW, inv, hp, agg, N);
    scatter_kernel<<<(E * 32 + TPB - 1) / TPB, TPB>>>(hp, src, dst, agg, E);
    epilogue_kernel<false><<<(total4 + TPB - 1) / TPB, TPB>>>(agg, inv, gb, feat, total4);

    // --- bucketed context gather-GEMM (fragment layout, double-buffered) ---
    ctx_gemm_tc_kernel<<<gemm_grid, TPB>>>(feat, perm, label, clen, rW, rb, out, N);
}

// round 14
// speedup vs baseline: 1.0482x; 1.0482x over previous
#include <cuda_runtime.h>
#include <cstdint>

#define N_MAX   50000
#define HDIM    256
#define E_MAX   800000
#define MAXCTX  8

// ---------------------------------------------------------------------------
// Scratch (device globals -- no allocation allowed in kernel_launch)
// ---------------------------------------------------------------------------
__device__ float g_h[N_MAX * HDIM];     // h' = (A @ W) * inv[row]
__device__ float g_agg[N_MAX * HDIM];   // scatter accumulator
__device__ float g_feat[N_MAX * HDIM];  // layer output (feat1 then feat2)
__device__ float g_inv[N_MAX];          // deg, then rsqrt(deg)
__device__ int   g_bcnt[MAXCTX];        // bucket counts (clen in 0..7)
__device__ int   g_boff[MAXCTX];        // bucket offsets (mutated by scatter)
__device__ int   g_perm[N_MAX];         // rows sorted by context_len

// ---------------------------------------------------------------------------
// Fused setup kernels (launch overhead trimmed: 7 -> 4 small kernels)
// ---------------------------------------------------------------------------
__global__ void setup_init_kernel(float* deg, int n) {
    int i = blockIdx.x * blockDim.x + threadIdx.x;
    if (i < n) deg[i] = 1.0f;                       // self loop
    if (blockIdx.x == 0 && threadIdx.x < MAXCTX) g_bcnt[threadIdx.x] = 0;
}

__global__ void setup_count_kernel(const int* __restrict__ dst, float* deg, int e,
                                   const int* __restrict__ clen, int n) {
    int i = blockIdx.x * blockDim.x + threadIdx.x;
    if (i < e) atomicAdd(&deg[dst[i]], 1.0f);
    if (i < n) atomicAdd(&g_bcnt[clen[i]], 1);
}

__global__ void setup_scan_kernel(float* deg, int n) {
    int i = blockIdx.x * blockDim.x + threadIdx.x;
    if (i < n) deg[i] = rsqrtf(deg[i]);
    if (blockIdx.x == 0 && threadIdx.x == 0) {      // tiny serial scan (8 bins)
        int acc = 0;
        for (int b = 0; b < MAXCTX; ++b) { g_boff[b] = acc; acc += g_bcnt[b]; }
    }
}

__global__ void bucket_scatter_kernel(const int* __restrict__ clen, int n) {
    int i = blockIdx.x * blockDim.x + threadIdx.x;
    if (i < n) {
        int p = atomicAdd(&g_boff[clen[i]], 1);
        g_perm[p] = i;
    }
}

// ---------------------------------------------------------------------------
// SGEMM (fp32 SIMT, at FFMA roofline): hprime = (A@W)*inv; agg = hprime
// BM=128, BN=128, BK=16, 256 threads, 8x8 per thread
// ---------------------------------------------------------------------------
__global__ __launch_bounds__(256) void sgemm_fused_kernel(
    const float* __restrict__ A, const float* __restrict__ B,
    const float* __restrict__ inv,
    float* __restrict__ hprime, float* __restrict__ agg, int M)
{
    const int K = 256;
    __shared__ float As[16][128];   // transposed: As[k][m]
    __shared__ float Bs[16][128];

    const int block_row = blockIdx.x * 128;
    const int block_col = blockIdx.y * 128;
    const int tid = threadIdx.x;
    const int tr = tid >> 4;
    const int tc = tid & 15;

    const int a_row0 = tid >> 2;
    const int a_col  = (tid & 3) * 4;
    const int b_row0 = tid >> 5;
    const int b_col  = (tid & 31) * 4;

    float acc[8][8] = {};

    for (int k0 = 0; k0 < K; k0 += 16) {
        #pragma unroll
        for (int it = 0; it < 2; ++it) {
            int m = a_row0 + it * 64;
            int gr = block_row + m;
            float4 v = make_float4(0.f, 0.f, 0.f, 0.f);
            if (gr < M) v = *(const float4*)(A + (size_t)gr * K + k0 + a_col);
            As[a_col + 0][m] = v.x;
            As[a_col + 1][m] = v.y;
            As[a_col + 2][m] = v.z;
            As[a_col + 3][m] = v.w;
        }
        #pragma unroll
        for (int it = 0; it < 2; ++it) {
            int kk = b_row0 + it * 8;
            *(float4*)&Bs[kk][b_col] =
                *(const float4*)(B + (size_t)(k0 + kk) * 256 + block_col + b_col);
        }
        __syncthreads();

        #pragma unroll
        for (int kk = 0; kk < 16; ++kk) {
            float4 a0 = *(const float4*)&As[kk][tr * 8];
            float4 a1 = *(const float4*)&As[kk][tr * 8 + 4];
            float4 b0 = *(const float4*)&Bs[kk][tc * 8];
            float4 b1 = *(const float4*)&Bs[kk][tc * 8 + 4];
            float ar[8] = {a0.x, a0.y, a0.z, a0.w, a1.x, a1.y, a1.z, a1.w};
            float br[8] = {b0.x, b0.y, b0.z, b0.w, b1.x, b1.y, b1.z, b1.w};
            #pragma unroll
            for (int i = 0; i < 8; ++i)
                #pragma unroll
                for (int j = 0; j < 8; ++j)
                    acc[i][j] += ar[i] * br[j];
        }
        __syncthreads();
    }

    #pragma unroll
    for (int i = 0; i < 8; ++i) {
        int gr = block_row + tr * 8 + i;
        if (gr < M) {
            float iv = inv[gr];
            #pragma unroll
            for (int j = 0; j < 8; j += 4) {
                float4 o = make_float4(acc[i][j] * iv, acc[i][j+1] * iv,
                                       acc[i][j+2] * iv, acc[i][j+3] * iv);
                size_t off = (size_t)gr * 256 + block_col + tc * 8 + j;
                *(float4*)(hprime + off) = o;
                *(float4*)(agg    + off) = o;
            }
        }
    }
}

// ---------------------------------------------------------------------------
// Edge scatter: agg[dst,:] += hprime[src,:]   (pure vectorized reductions)
// ---------------------------------------------------------------------------
__global__ void scatter_kernel(const float* __restrict__ hp,
                               const int* __restrict__ src,
                               const int* __restrict__ dst,
                               float* __restrict__ agg, int e)
{
    int warp = (blockIdx.x * blockDim.x + threadIdx.x) >> 5;
    int lane = threadIdx.x & 31;
    if (warp >= e) return;
    int s = __ldg(&src[warp]);
    int d = __ldg(&dst[warp]);
    const float4* hpp = (const float4*)(hp + (size_t)s * 256);
    float* ap = agg + (size_t)d * 256;
    #pragma unroll
    for (int it = 0; it < 2; ++it) {
        int idx = lane + it * 32;
        float4 v = hpp[idx];
        asm volatile("red.global.add.v4.f32 [%0], {%1, %2, %3, %4};"
                     :: "l"(ap + (size_t)idx * 4),
                        "f"(v.x), "f"(v.y), "f"(v.z), "f"(v.w)
                     : "memory");
    }
}

// ---------------------------------------------------------------------------
// Epilogue: feat = agg * inv[row] + b, optional relu
// ---------------------------------------------------------------------------
template <bool RELU>
__global__ void epilogue_kernel(const float* __restrict__ agg,
                                const float* __restrict__ inv,
                                const float* __restrict__ b,
                                float* __restrict__ feat, int total4)
{
    int t = blockIdx.x * blockDim.x + threadIdx.x;
    if (t >= total4) return;
    int row = t >> 6;
    int c4  = t & 63;
    float iv = inv[row];
    float4 v  = ((const float4*)agg)[t];
    float4 bb = ((const float4*)b)[c4];
    v.x = v.x * iv + bb.x; v.y = v.y * iv + bb.y;
    v.z = v.z * iv + bb.z; v.w = v.w * iv + bb.w;
    if (RELU) {
        v.x = fmaxf(v.x, 0.f); v.y = fmaxf(v.y, 0.f);
        v.z = fmaxf(v.z, 0.f); v.w = fmaxf(v.w, 0.f);
    }
    ((float4*)feat)[t] = v;
}

// ---------------------------------------------------------------------------
// TF32 helpers
// ---------------------------------------------------------------------------
__device__ __forceinline__ uint32_t f2tf(float x) {
    uint32_t r;
    asm("cvt.rna.tf32.f32 %0, %1;" : "=r"(r) : "f"(x));
    return r;
}

__device__ __forceinline__ void mma_tf32(float d[4], const uint32_t a[4],
                                         const uint32_t b[2]) {
    asm volatile(
        "mma.sync.aligned.m16n8k8.row.col.f32.tf32.tf32.f32 "
        "{%0,%1,%2,%3}, {%4,%5,%6,%7}, {%8,%9}, {%0,%1,%2,%3};"
        : "+f"(d[0]), "+f"(d[1]), "+f"(d[2]), "+f"(d[3])
        : "r"(a[0]), "r"(a[1]), "r"(a[2]), "r"(a[3]),
          "r"(b[0]), "r"(b[1]));
}

// ---------------------------------------------------------------------------
// Context GEMM, TF32 TC, R6/R12-proven layout, BK=16 for low regs/smem so
// __launch_bounds__(256,2) gives 2 CTAs/SM (barrier stalls interleave).
// Bucketed rows + fused final product:
//   out[row,c] = feat2[row,c] * ( sum_{j<len[row]} feat2[label[row,j],:]
//                                 @ Wr[j*256:, c]  + rb[c] )
// BM=128, BN=128, BK=16, 8 warps (2x4), warp tile 64x32 via m16n8k8.
// ---------------------------------------------------------------------------
__global__ __launch_bounds__(256, 2) void ctx_gemm_tc_kernel(
    const float* __restrict__ feat,
    const int* __restrict__ perm,      // [M] rows sorted by clen
    const int* __restrict__ label,     // [M, 8]
    const int* __restrict__ clen,      // [M]
    const float* __restrict__ Wr,      // [2048, 256]
    const float* __restrict__ rb,      // [256]
    float* __restrict__ out, int M)
{
    __shared__ uint32_t As[16][132];    // logical A[k][m], padded (8.4 KB)
    __shared__ uint32_t Bsp[8][260];    // B k-pair interleaved   (8.3 KB)
    __shared__ int s_label[128][MAXCTX];
    __shared__ int s_len[128];
    __shared__ int s_row[128];
    __shared__ int s_maxlen;

    const int brow = blockIdx.x * 128;
    const int bcol = blockIdx.y * 128;
    const int tid  = threadIdx.x;
    const int lane = tid & 31;
    const int warp = tid >> 5;
    const int g    = lane >> 2;   // 0..7
    const int tig  = lane & 3;    // 0..3
    const int wm   = warp & 1;    // warp row (2)
    const int wn   = warp >> 1;   // warp col (4)

    // --- stage per-row metadata through the permutation ---
    if (tid < 128) {
        int gi = brow + tid;
        int row = (gi < M) ? perm[gi] : -1;
        s_row[tid] = row;
        s_len[tid] = (row >= 0) ? clen[row] : 0;
    }
    __syncthreads();
    for (int i = tid; i < 128 * MAXCTX; i += 256) {
        int r = i >> 3, j = i & 7;
        int row = s_row[r];
        s_label[r][j] = (row >= 0) ? label[(size_t)row * MAXCTX + j] : 0;
    }
    if (warp == 0) {
        int v = max(max(s_len[lane], s_len[lane + 32]),
                    max(s_len[lane + 64], s_len[lane + 96]));
        #pragma unroll
        for (int o = 16; o; o >>= 1) v = max(v, __shfl_xor_sync(0xffffffffu, v, o));
        if (lane == 0) s_maxlen = v;
    }
    __syncthreads();
    const int K_eff = s_maxlen * 256;   // bucketed: ~= len(bucket)*256

    float acc[4][4][4];
    #pragma unroll
    for (int i = 0; i < 4; ++i)
        #pragma unroll
        for (int j = 0; j < 4; ++j)
            #pragma unroll
            for (int c = 0; c < 4; ++c) acc[i][j][c] = 0.f;

    // loader indices (BK=16: 128x16 A floats, 16x128 B floats; 2 float4/thread)
    const int lm  = tid >> 1;          // A row 0..127
    const int lkb = (tid & 1) * 8;     // A k-base 0 / 8
    const int bkk = tid & 15;          // B k-row 0..15
    const int bnb = (tid >> 4) * 8;    // B n-base 0..120

    float4 rA[2], rB[2];

    auto loadTiles = [&](int k0) {
        const int j   = k0 >> 8;            // context slot (constant in a tile)
        const int kc0 = (k0 & 255) + lkb;
        const int L   = s_len[lm];
        const float* abase = feat + (size_t)s_label[lm][j] * HDIM + kc0;
        #pragma unroll
        for (int it = 0; it < 2; ++it) {
            float4 v = make_float4(0.f, 0.f, 0.f, 0.f);
            if (j < L) v = *(const float4*)(abase + it * 4);
            rA[it] = v;
        }
        const float* bbase = Wr + (size_t)(k0 + bkk) * HDIM + bcol + bnb;
        #pragma unroll
        for (int it = 0; it < 2; ++it)
            rB[it] = *(const float4*)(bbase + it * 4);
    };

    const int bprow = (bkk >> 3) * 4 + (bkk & 3);   // 0..7
    const int bkh   = (bkk >> 2) & 1;

    auto storeTiles = [&]() {
        #pragma unroll
        for (int it = 0; it < 2; ++it) {
            int k = lkb + it * 4;
            As[k + 0][lm] = f2tf(rA[it].x);
            As[k + 1][lm] = f2tf(rA[it].y);
            As[k + 2][lm] = f2tf(rA[it].z);
            As[k + 3][lm] = f2tf(rA[it].w);
        }
        #pragma unroll
        for (int it = 0; it < 2; ++it) {
            int n = bnb + it * 4;
            Bsp[bprow][2 * (n + 0) + bkh] = f2tf(rB[it].x);
            Bsp[bprow][2 * (n + 1) + bkh] = f2tf(rB[it].y);
            Bsp[bprow][2 * (n + 2) + bkh] = f2tf(rB[it].z);
            Bsp[bprow][2 * (n + 3) + bkh] = f2tf(rB[it].w);
        }
    };

    if (K_eff > 0) {
        loadTiles(0);
        storeTiles();
        __syncthreads();

        for (int k0 = 0; k0 < K_eff; k0 += 16) {
            bool more = (k0 + 16) < K_eff;
            if (more) loadTiles(k0 + 16);   // global prefetch under the MMAs

            #pragma unroll
            for (int ks = 0; ks < 2; ++ks) {
                uint32_t af[4][4], bf[4][2];
                #pragma unroll
                for (int i = 0; i < 4; ++i) {
                    int mb = wm * 64 + i * 16 + g;
                    af[i][0] = As[ks * 8 + tig    ][mb];
                    af[i][1] = As[ks * 8 + tig    ][mb + 8];
                    af[i][2] = As[ks * 8 + tig + 4][mb];
                    af[i][3] = As[ks * 8 + tig + 4][mb + 8];
                }
                #pragma unroll
                for (int jn = 0; jn < 4; ++jn) {
                    int n = wn * 32 + jn * 8 + g;
                    uint2 bb = *(const uint2*)&Bsp[ks * 4 + tig][2 * n];
                    bf[jn][0] = bb.x;
                    bf[jn][1] = bb.y;
                }
                #pragma unroll
                for (int i = 0; i < 4; ++i)
                    #pragma unroll
                    for (int jn = 0; jn < 4; ++jn)
                        mma_tf32(acc[i][jn], af[i], bf[jn]);
            }
            __syncthreads();
            if (more) { storeTiles(); __syncthreads(); }
        }
    }

    // fused epilogue through permutation: out[row] = feat2[row] * (acc + rb)
    #pragma unroll
    for (int i = 0; i < 4; ++i) {
        int lr0 = wm * 64 + i * 16 + g;
        int lr1 = lr0 + 8;
        int row0 = s_row[lr0];
        int row1 = s_row[lr1];
        #pragma unroll
        for (int jn = 0; jn < 4; ++jn) {
            int c = bcol + wn * 32 + jn * 8 + tig * 2;
            float2 bv = *(const float2*)(rb + c);
            if (row0 >= 0) {
                float2 fv = *(const float2*)(feat + (size_t)row0 * HDIM + c);
                float2 o;
                o.x = (acc[i][jn][0] + bv.x) * fv.x;
                o.y = (acc[i][jn][1] + bv.y) * fv.y;
                *(float2*)(out + (size_t)row0 * HDIM + c) = o;
            }
            if (row1 >= 0) {
                float2 fv = *(const float2*)(feat + (size_t)row1 * HDIM + c);
                float2 o;
                o.x = (acc[i][jn][2] + bv.x) * fv.x;
                o.y = (acc[i][jn][3] + bv.y) * fv.y;
                *(float2*)(out + (size_t)row1 * HDIM + c) = o;
            }
        }
    }
}

// ---------------------------------------------------------------------------
// Launch
// ---------------------------------------------------------------------------
extern "C" void kernel_launch(void* const* d_in, const int* in_sizes, int n_in,
                              void* d_out, int out_size)
{
    const float* x     = (const float*)d_in[0];
    const int*   ei    = (const int*)  d_in[1];   // [2, E]: src row then dst row
    const int*   label = (const int*)  d_in[2];
    const int*   clen  = (const int*)  d_in[3];
    const float* gW    = (const float*)d_in[4];
    const float* gb    = (const float*)d_in[5];
    const float* rW    = (const float*)d_in[6];
    const float* rb    = (const float*)d_in[7];
    float*       out   = (float*)d_out;

    const int N = in_sizes[3];
    const int E = in_sizes[1] / 2;
    const int* src = ei;
    const int* dst = ei + E;

    float *hp, *agg, *feat, *inv;
    int *perm;
    cudaGetSymbolAddress((void**)&hp,   g_h);
    cudaGetSymbolAddress((void**)&agg,  g_agg);
    cudaGetSymbolAddress((void**)&feat, g_feat);
    cudaGetSymbolAddress((void**)&inv,  g_inv);
    cudaGetSymbolAddress((void**)&perm, g_perm);

    const int total4 = N * (HDIM / 4);
    const int TPB = 256;
    const int big = (E > N) ? E : N;
    dim3 gemm_grid((N + 127) / 128, 2);   // BN=128 -> 2 column blocks

    // --- normalization + length bucketing (fused setup) ---
    setup_init_kernel<<<(N + TPB - 1) / TPB, TPB>>>(inv, N);
    setup_count_kernel<<<(big + TPB - 1) / TPB, TPB>>>(dst, inv, E, clen, N);
    setup_scan_kernel<<<(N + TPB - 1) / TPB, TPB>>>(inv, N);
    bucket_scatter_kernel<<<(N + TPB - 1) / TPB, TPB>>>(clen, N);

    // --- GCN layer 1: feat1 = relu(inv*scatter(h') + b), h' = (x@W)*inv ---
    sgemm_fused_kernel<<<gemm_grid, TPB>>>(x, gW, inv, hp, agg, N);
    scatter_kernel<<<(E * 32 + TPB - 1) / TPB, TPB>>>(hp, src, dst, agg, E);
    epilogue_kernel<true><<<(total4 + TPB - 1) / TPB, TPB>>>(agg, inv, gb, feat, total4);

    // --- GCN layer 2 ---
    sgemm_fused_kernel<<<gemm_grid, TPB>>>(feat, gW, inv, hp, agg, N);
    scatter_kernel<<<(E * 32 + TPB - 1) / TPB, TPB>>>(hp, src, dst, agg, E);
    epilogue_kernel<false><<<(total4 + TPB - 1) / TPB, TPB>>>(agg, inv, gb, feat, total4);

    // --- bucketed context gather-GEMM (BK=16, 2 CTAs/SM), fused final ---
    ctx_gemm_tc_kernel<<<gemm_grid, TPB>>>(feat, perm, label, clen, rW, rb, out, N);
}

// round 15
// speedup vs baseline: 1.1601x; 1.1068x over previous
#include <cuda_runtime.h>
#include <cuda_fp16.h>
#include <cstdint>

#define N_MAX   50000
#define HDIM    256
#define E_MAX   800000
#define MAXCTX  8

// ---------------------------------------------------------------------------
// Scratch (device globals -- no allocation allowed in kernel_launch)
// ---------------------------------------------------------------------------
__device__ float g_h[N_MAX * HDIM];     // h' = (A @ W) * inv[row]
__device__ float g_agg[N_MAX * HDIM];   // scatter accumulator
__device__ float g_feat[N_MAX * HDIM];  // layer output (feat1 then feat2)
__device__ float g_inv[N_MAX];          // deg, then rsqrt(deg)
__device__ int   g_bcnt[MAXCTX];        // bucket counts (clen in 0..7)
__device__ int   g_boff[MAXCTX];        // bucket offsets (mutated by scatter)
__device__ int   g_perm[N_MAX];         // rows sorted by context_len

// ---------------------------------------------------------------------------
// Fused setup kernels
// ---------------------------------------------------------------------------
__global__ void setup_init_kernel(float* deg, int n) {
    int i = blockIdx.x * blockDim.x + threadIdx.x;
    if (i < n) deg[i] = 1.0f;                       // self loop
    if (blockIdx.x == 0 && threadIdx.x < MAXCTX) g_bcnt[threadIdx.x] = 0;
}

__global__ void setup_count_kernel(const int* __restrict__ dst, float* deg, int e,
                                   const int* __restrict__ clen, int n) {
    int i = blockIdx.x * blockDim.x + threadIdx.x;
    if (i < e) atomicAdd(&deg[dst[i]], 1.0f);
    if (i < n) atomicAdd(&g_bcnt[clen[i]], 1);
}

__global__ void setup_scan_kernel(float* deg, int n) {
    int i = blockIdx.x * blockDim.x + threadIdx.x;
    if (i < n) deg[i] = rsqrtf(deg[i]);
    if (blockIdx.x == 0 && threadIdx.x == 0) {      // tiny serial scan (8 bins)
        int acc = 0;
        for (int b = 0; b < MAXCTX; ++b) { g_boff[b] = acc; acc += g_bcnt[b]; }
    }
}

__global__ void bucket_scatter_kernel(const int* __restrict__ clen, int n) {
    int i = blockIdx.x * blockDim.x + threadIdx.x;
    if (i < n) {
        int p = atomicAdd(&g_boff[clen[i]], 1);
        g_perm[p] = i;
    }
}

// ---------------------------------------------------------------------------
// SGEMM (fp32 SIMT, at FFMA roofline): hprime = (A@W)*inv; agg = hprime
// BM=128, BN=128, BK=16, 256 threads, 8x8 per thread
// ---------------------------------------------------------------------------
__global__ __launch_bounds__(256) void sgemm_fused_kernel(
    const float* __restrict__ A, const float* __restrict__ B,
    const float* __restrict__ inv,
    float* __restrict__ hprime, float* __restrict__ agg, int M)
{
    const int K = 256;
    __shared__ float As[16][128];   // transposed: As[k][m]
    __shared__ float Bs[16][128];

    const int block_row = blockIdx.x * 128;
    const int block_col = blockIdx.y * 128;
    const int tid = threadIdx.x;
    const int tr = tid >> 4;
    const int tc = tid & 15;

    const int a_row0 = tid >> 2;
    const int a_col  = (tid & 3) * 4;
    const int b_row0 = tid >> 5;
    const int b_col  = (tid & 31) * 4;

    float acc[8][8] = {};

    for (int k0 = 0; k0 < K; k0 += 16) {
        #pragma unroll
        for (int it = 0; it < 2; ++it) {
            int m = a_row0 + it * 64;
            int gr = block_row + m;
            float4 v = make_float4(0.f, 0.f, 0.f, 0.f);
            if (gr < M) v = *(const float4*)(A + (size_t)gr * K + k0 + a_col);
            As[a_col + 0][m] = v.x;
            As[a_col + 1][m] = v.y;
            As[a_col + 2][m] = v.z;
            As[a_col + 3][m] = v.w;
        }
        #pragma unroll
        for (int it = 0; it < 2; ++it) {
            int kk = b_row0 + it * 8;
            *(float4*)&Bs[kk][b_col] =
                *(const float4*)(B + (size_t)(k0 + kk) * 256 + block_col + b_col);
        }
        __syncthreads();

        #pragma unroll
        for (int kk = 0; kk < 16; ++kk) {
            float4 a0 = *(const float4*)&As[kk][tr * 8];
            float4 a1 = *(const float4*)&As[kk][tr * 8 + 4];
            float4 b0 = *(const float4*)&Bs[kk][tc * 8];
            float4 b1 = *(const float4*)&Bs[kk][tc * 8 + 4];
            float ar[8] = {a0.x, a0.y, a0.z, a0.w, a1.x, a1.y, a1.z, a1.w};
            float br[8] = {b0.x, b0.y, b0.z, b0.w, b1.x, b1.y, b1.z, b1.w};
            #pragma unroll
            for (int i = 0; i < 8; ++i)
                #pragma unroll
                for (int j = 0; j < 8; ++j)
                    acc[i][j] += ar[i] * br[j];
        }
        __syncthreads();
    }

    #pragma unroll
    for (int i = 0; i < 8; ++i) {
        int gr = block_row + tr * 8 + i;
        if (gr < M) {
            float iv = inv[gr];
            #pragma unroll
            for (int j = 0; j < 8; j += 4) {
                float4 o = make_float4(acc[i][j] * iv, acc[i][j+1] * iv,
                                       acc[i][j+2] * iv, acc[i][j+3] * iv);
                size_t off = (size_t)gr * 256 + block_col + tc * 8 + j;
                *(float4*)(hprime + off) = o;
                *(float4*)(agg    + off) = o;
            }
        }
    }
}

// ---------------------------------------------------------------------------
// Edge scatter: agg[dst,:] += hprime[src,:]   (pure vectorized reductions)
// ---------------------------------------------------------------------------
__global__ void scatter_kernel(const float* __restrict__ hp,
                               const int* __restrict__ src,
                               const int* __restrict__ dst,
                               float* __restrict__ agg, int e)
{
    int warp = (blockIdx.x * blockDim.x + threadIdx.x) >> 5;
    int lane = threadIdx.x & 31;
    if (warp >= e) return;
    int s = __ldg(&src[warp]);
    int d = __ldg(&dst[warp]);
    const float4* hpp = (const float4*)(hp + (size_t)s * 256);
    float* ap = agg + (size_t)d * 256;
    #pragma unroll
    for (int it = 0; it < 2; ++it) {
        int idx = lane + it * 32;
        float4 v = hpp[idx];
        asm volatile("red.global.add.v4.f32 [%0], {%1, %2, %3, %4};"
                     :: "l"(ap + (size_t)idx * 4),
                        "f"(v.x), "f"(v.y), "f"(v.z), "f"(v.w)
                     : "memory");
    }
}

// ---------------------------------------------------------------------------
// Epilogue: feat = agg * inv[row] + b, optional relu
// ---------------------------------------------------------------------------
template <bool RELU>
__global__ void epilogue_kernel(const float* __restrict__ agg,
                                const float* __restrict__ inv,
                                const float* __restrict__ b,
                                float* __restrict__ feat, int total4)
{
    int t = blockIdx.x * blockDim.x + threadIdx.x;
    if (t >= total4) return;
    int row = t >> 6;
    int c4  = t & 63;
    float iv = inv[row];
    float4 v  = ((const float4*)agg)[t];
    float4 bb = ((const float4*)b)[c4];
    v.x = v.x * iv + bb.x; v.y = v.y * iv + bb.y;
    v.z = v.z * iv + bb.z; v.w = v.w * iv + bb.w;
    if (RELU) {
        v.x = fmaxf(v.x, 0.f); v.y = fmaxf(v.y, 0.f);
        v.z = fmaxf(v.z, 0.f); v.w = fmaxf(v.w, 0.f);
    }
    ((float4*)feat)[t] = v;
}

// ---------------------------------------------------------------------------
// FP16 helpers
// ---------------------------------------------------------------------------
__device__ __forceinline__ uint32_t f2h2(float lo, float hi) {
    __half2 h = __floats2half2_rn(lo, hi);
    return *(uint32_t*)&h;
}

__device__ __forceinline__ void mma_f16(float d[4], const uint32_t a[4],
                                        const uint32_t b[2]) {
    asm volatile(
        "mma.sync.aligned.m16n8k16.row.col.f32.f16.f16.f32 "
        "{%0,%1,%2,%3}, {%4,%5,%6,%7}, {%8,%9}, {%0,%1,%2,%3};"
        : "+f"(d[0]), "+f"(d[1]), "+f"(d[2]), "+f"(d[3])
        : "r"(a[0]), "r"(a[1]), "r"(a[2]), "r"(a[3]),
          "r"(b[0]), "r"(b[1]));
}

// ---------------------------------------------------------------------------
// Context GEMM, FP16 tensor cores (m16n8k16), R12-proven layout with k-PAIR
// words (half2). Same indexing pattern as the validated tf32 kernel: A frag
// = 4x LDS.32 at rows (tig, tig+4) x (mb, mb+8) of the k-pair array; B frag
// = 1x LDS.64 via the k-pair interleave. Half the MMAs, half the LDS, half
// the smem of the tf32 version.
//   out[row,c] = feat2[row,c] * ( sum_{j<len[row]} feat2[label[row,j],:]
//                                 @ Wr[j*256:, c]  + rb[c] )
// BM=128, BN=128, BK=32 (= 2 k-steps of 16), 8 warps (2x4), warp tile 64x32.
// ---------------------------------------------------------------------------
__global__ __launch_bounds__(256) void ctx_gemm_tc_kernel(
    const float* __restrict__ feat,
    const int* __restrict__ perm,      // [M] rows sorted by clen
    const int* __restrict__ label,     // [M, 8]
    const int* __restrict__ clen,      // [M]
    const float* __restrict__ Wr,      // [2048, 256]
    const float* __restrict__ rb,      // [256]
    float* __restrict__ out, int M)
{
    __shared__ uint32_t As2[16][132];   // A k-pairs: As2[kp][m] = (A[m][2kp],A[m][2kp+1])
    __shared__ uint32_t Bsp[8][260];    // B k-pair interleave: [bprow][2n+kh]
    __shared__ int s_label[128][MAXCTX];
    __shared__ int s_len[128];
    __shared__ int s_row[128];
    __shared__ int s_maxlen;

    const int brow = blockIdx.x * 128;
    const int bcol = blockIdx.y * 128;
    const int tid  = threadIdx.x;
    const int lane = tid & 31;
    const int warp = tid >> 5;
    const int g    = lane >> 2;   // 0..7
    const int tig  = lane & 3;    // 0..3
    const int wm   = warp & 1;    // warp row (2)
    const int wn   = warp >> 1;   // warp col (4)

    // --- stage per-row metadata through the permutation ---
    if (tid < 128) {
        int gi = brow + tid;
        int row = (gi < M) ? perm[gi] : -1;
        s_row[tid] = row;
        s_len[tid] = (row >= 0) ? clen[row] : 0;
    }
    __syncthreads();
    for (int i = tid; i < 128 * MAXCTX; i += 256) {
        int r = i >> 3, j = i & 7;
        int row = s_row[r];
        s_label[r][j] = (row >= 0) ? label[(size_t)row * MAXCTX + j] : 0;
    }
    if (warp == 0) {
        int v = max(max(s_len[lane], s_len[lane + 32]),
                    max(s_len[lane + 64], s_len[lane + 96]));
        #pragma unroll
        for (int o = 16; o; o >>= 1) v = max(v, __shfl_xor_sync(0xffffffffu, v, o));
        if (lane == 0) s_maxlen = v;
    }
    __syncthreads();
    const int K_eff = s_maxlen * 256;   // bucketed: ~= len(bucket)*256

    float acc[4][4][4];
    #pragma unroll
    for (int i = 0; i < 4; ++i)
        #pragma unroll
        for (int j = 0; j < 4; ++j)
            #pragma unroll
            for (int c = 0; c < 4; ++c) acc[i][j][c] = 0.f;

    // A loader: thread covers row lm, 16 consecutive k at lkb
    const int lm  = tid >> 1;          // A row 0..127
    const int lkb = (tid & 1) * 16;    // A k-base 0 / 16
    // B loader: thread covers k-pair bkp (rows 2bkp, 2bkp+1), 8 n at bnb
    const int bkp = tid & 15;          // k-pair 0..15
    const int bnb = (tid >> 4) * 8;    // n base 0..120

    float4 rA[4], rB0[2], rB1[2];

    auto loadTiles = [&](int k0) {
        const int j   = k0 >> 8;            // context slot (constant in a tile)
        const int kc0 = (k0 & 255) + lkb;
        const int L   = s_len[lm];
        const float* abase = feat + (size_t)s_label[lm][j] * HDIM + kc0;
        #pragma unroll
        for (int it = 0; it < 4; ++it) {
            float4 v = make_float4(0.f, 0.f, 0.f, 0.f);
            if (j < L) v = *(const float4*)(abase + it * 4);
            rA[it] = v;
        }
        const float* b0 = Wr + (size_t)(k0 + 2 * bkp)     * HDIM + bcol + bnb;
        const float* b1 = Wr + (size_t)(k0 + 2 * bkp + 1) * HDIM + bcol + bnb;
        rB0[0] = *(const float4*)b0;  rB0[1] = *(const float4*)(b0 + 4);
        rB1[0] = *(const float4*)b1;  rB1[1] = *(const float4*)(b1 + 4);
    };

    const int bprow = (bkp >> 3) * 4 + (bkp & 3);   // 0..7
    const int bkh   = (bkp >> 2) & 1;

    auto storeTiles = [&]() {
        // A: 16 floats = 8 k-pair half2 words
        const float av[16] = {rA[0].x, rA[0].y, rA[0].z, rA[0].w,
                              rA[1].x, rA[1].y, rA[1].z, rA[1].w,
                              rA[2].x, rA[2].y, rA[2].z, rA[2].w,
                              rA[3].x, rA[3].y, rA[3].z, rA[3].w};
        const int kpb = lkb >> 1;   // 0 or 8
        #pragma unroll
        for (int o = 0; o < 8; ++o)
            As2[kpb + o][lm] = f2h2(av[2 * o], av[2 * o + 1]);
        // B: pair rows 2bkp / 2bkp+1 per column
        const float b0v[8] = {rB0[0].x, rB0[0].y, rB0[0].z, rB0[0].w,
                              rB0[1].x, rB0[1].y, rB0[1].z, rB0[1].w};
        const float b1v[8] = {rB1[0].x, rB1[0].y, rB1[0].z, rB1[0].w,
                              rB1[1].x, rB1[1].y, rB1[1].z, rB1[1].w};
        #pragma unroll
        for (int c = 0; c < 8; ++c)
            Bsp[bprow][2 * (bnb + c) + bkh] = f2h2(b0v[c], b1v[c]);
    };

    if (K_eff > 0) {
        loadTiles(0);
        storeTiles();
        __syncthreads();

        for (int k0 = 0; k0 < K_eff; k0 += 32) {
            bool more = (k0 + 32) < K_eff;
            if (more) loadTiles(k0 + 32);   // global prefetch under the MMAs

            #pragma unroll
            for (int ks = 0; ks < 2; ++ks) {    // 2 k-steps of 16
                uint32_t af[4][4], bf[4][2];
                #pragma unroll
                for (int i = 0; i < 4; ++i) {
                    int mb = wm * 64 + i * 16 + g;
                    af[i][0] = As2[ks * 8 + tig    ][mb];       // rows g,   k 2tig..+1
                    af[i][1] = As2[ks * 8 + tig    ][mb + 8];   // rows g+8
                    af[i][2] = As2[ks * 8 + tig + 4][mb];       // rows g,   k 2tig+8..+9
                    af[i][3] = As2[ks * 8 + tig + 4][mb + 8];   // rows g+8
                }
                #pragma unroll
                for (int jn = 0; jn < 4; ++jn) {
                    int n = wn * 32 + jn * 8 + g;
                    uint2 bb = *(const uint2*)&Bsp[ks * 4 + tig][2 * n];
                    bf[jn][0] = bb.x;   // k-pair tig   (k 2tig..+1)
                    bf[jn][1] = bb.y;   // k-pair tig+4 (k 2tig+8..+9)
                }
                #pragma unroll
                for (int i = 0; i < 4; ++i)
                    #pragma unroll
                    for (int jn = 0; jn < 4; ++jn)
                        mma_f16(acc[i][jn], af[i], bf[jn]);
            }
            __syncthreads();
            if (more) { storeTiles(); __syncthreads(); }
        }
    }

    // fused epilogue through permutation: out[row] = feat2[row] * (acc + rb)
    #pragma unroll
    for (int i = 0; i < 4; ++i) {
        int lr0 = wm * 64 + i * 16 + g;
        int lr1 = lr0 + 8;
        int row0 = s_row[lr0];
        int row1 = s_row[lr1];
        #pragma unroll
        for (int jn = 0; jn < 4; ++jn) {
            int c = bcol + wn * 32 + jn * 8 + tig * 2;
            float2 bv = *(const float2*)(rb + c);
            if (row0 >= 0) {
                float2 fv = *(const float2*)(feat + (size_t)row0 * HDIM + c);
                float2 o;
                o.x = (acc[i][jn][0] + bv.x) * fv.x;
                o.y = (acc[i][jn][1] + bv.y) * fv.y;
                *(float2*)(out + (size_t)row0 * HDIM + c) = o;
            }
            if (row1 >= 0) {
                float2 fv = *(const float2*)(feat + (size_t)row1 * HDIM + c);
                float2 o;
                o.x = (acc[i][jn][2] + bv.x) * fv.x;
                o.y = (acc[i][jn][3] + bv.y) * fv.y;
                *(float2*)(out + (size_t)row1 * HDIM + c) = o;
            }
        }
    }
}

// ---------------------------------------------------------------------------
// Launch
// ---------------------------------------------------------------------------
extern "C" void kernel_launch(void* const* d_in, const int* in_sizes, int n_in,
                              void* d_out, int out_size)
{
    const float* x     = (const float*)d_in[0];
    const int*   ei    = (const int*)  d_in[1];   // [2, E]: src row then dst row
    const int*   label = (const int*)  d_in[2];
    const int*   clen  = (const int*)  d_in[3];
    const float* gW    = (const float*)d_in[4];
    const float* gb    = (const float*)d_in[5];
    const float* rW    = (const float*)d_in[6];
    const float* rb    = (const float*)d_in[7];
    float*       out   = (float*)d_out;

    const int N = in_sizes[3];
    const int E = in_sizes[1] / 2;
    const int* src = ei;
    const int* dst = ei + E;

    float *hp, *agg, *feat, *inv;
    int *perm;
    cudaGetSymbolAddress((void**)&hp,   g_h);
    cudaGetSymbolAddress((void**)&agg,  g_agg);
    cudaGetSymbolAddress((void**)&feat, g_feat);
    cudaGetSymbolAddress((void**)&inv,  g_inv);
    cudaGetSymbolAddress((void**)&perm, g_perm);

    const int total4 = N * (HDIM / 4);
    const int TPB = 256;
    const int big = (E > N) ? E : N;
    dim3 gemm_grid((N + 127) / 128, 2);   // BN=128 -> 2 column blocks

    // --- normalization + length bucketing (fused setup) ---
    setup_init_kernel<<<(N + TPB - 1) / TPB, TPB>>>(inv, N);
    setup_count_kernel<<<(big + TPB - 1) / TPB, TPB>>>(dst, inv, E, clen, N);
    setup_scan_kernel<<<(N + TPB - 1) / TPB, TPB>>>(inv, N);
    bucket_scatter_kernel<<<(N + TPB - 1) / TPB, TPB>>>(clen, N);

    // --- GCN layer 1: feat1 = relu(inv*scatter(h') + b), h' = (x@W)*inv ---
    sgemm_fused_kernel<<<gemm_grid, TPB>>>(x, gW, inv, hp, agg, N);
    scatter_kernel<<<(E * 32 + TPB - 1) / TPB, TPB>>>(hp, src, dst, agg, E);
    epilogue_kernel<true><<<(total4 + TPB - 1) / TPB, TPB>>>(agg, inv, gb, feat, total4);

    // --- GCN layer 2 ---
    sgemm_fused_kernel<<<gemm_grid, TPB>>>(feat, gW, inv, hp, agg, N);
    scatter_kernel<<<(E * 32 + TPB - 1) / TPB, TPB>>>(hp, src, dst, agg, E);
    epilogue_kernel<false><<<(total4 + TPB - 1) / TPB, TPB>>>(agg, inv, gb, feat, total4);

    // --- bucketed context gather-GEMM (FP16 m16n8k16), fused final ---
    ctx_gemm_tc_kernel<<<gemm_grid, TPB>>>(feat, perm, label, clen, rW, rb, out, N);
}

// round 16
// speedup vs baseline: 1.3067x; 1.1264x over previous
#include <cuda_runtime.h>
#include <cuda_fp16.h>
#include <cstdint>

#define N_MAX   50000
#define HDIM    256
#define E_MAX   800000
#define MAXCTX  8

// ---------------------------------------------------------------------------
// Scratch (device globals -- no allocation allowed in kernel_launch)
// ---------------------------------------------------------------------------
__device__ float    g_h[N_MAX * HDIM];     // h' = (A @ W) * inv[row]
__device__ float    g_agg[N_MAX * HDIM];   // scatter accumulator
__device__ float    g_feat[N_MAX * HDIM];  // layer output (feat1 then feat2)
__device__ uint32_t g_feath[N_MAX * HDIM / 2]; // feat2 as half2 k-pairs
__device__ uint32_t g_wrp[(HDIM * MAXCTX / 2) * HDIM]; // Wr as half2 k-pair rows
__device__ float    g_inv[N_MAX];          // deg, then rsqrt(deg)
__device__ int      g_bcnt[MAXCTX];        // bucket counts (clen in 0..7)
__device__ int      g_boff[MAXCTX];        // bucket offsets (mutated by scatter)
__device__ int      g_perm[N_MAX];         // rows sorted by context_len (desc)

// ---------------------------------------------------------------------------
// Fused setup kernels
// ---------------------------------------------------------------------------
__global__ void setup_init_kernel(float* deg, int n) {
    int i = blockIdx.x * blockDim.x + threadIdx.x;
    if (i < n) deg[i] = 1.0f;                       // self loop
    if (blockIdx.x == 0 && threadIdx.x < MAXCTX) g_bcnt[threadIdx.x] = 0;
}

__global__ void setup_count_kernel(const int* __restrict__ dst, float* deg, int e,
                                   const int* __restrict__ clen, int n) {
    int i = blockIdx.x * blockDim.x + threadIdx.x;
    if (i < e) atomicAdd(&deg[dst[i]], 1.0f);
    if (i < n) atomicAdd(&g_bcnt[clen[i]], 1);
}

__global__ void setup_scan_kernel(float* deg, int n) {
    int i = blockIdx.x * blockDim.x + threadIdx.x;
    if (i < n) deg[i] = rsqrtf(deg[i]);
    if (blockIdx.x == 0 && threadIdx.x == 0) {
        // DESCENDING length order (LPT): longest blocks scheduled first
        int acc = 0;
        for (int b = MAXCTX - 1; b >= 0; --b) { g_boff[b] = acc; acc += g_bcnt[b]; }
    }
}

__global__ void bucket_scatter_kernel(const int* __restrict__ clen, int n) {
    int i = blockIdx.x * blockDim.x + threadIdx.x;
    if (i < n) {
        int p = atomicAdd(&g_boff[clen[i]], 1);
        g_perm[p] = i;
    }
}

// One-shot conversion: Wr[2048,256] fp32 -> k-pair half2 rows
//   wrp[kp*256 + n] = half2(Wr[2kp][n], Wr[2kp+1][n])
__global__ void wr_convert_kernel(const float* __restrict__ Wr, uint32_t* __restrict__ wrp) {
    int i = blockIdx.x * blockDim.x + threadIdx.x;   // 0 .. 1024*256-1
    int kp = i >> 8, n = i & 255;
    __half2 h = __floats2half2_rn(Wr[(2 * kp) * HDIM + n], Wr[(2 * kp + 1) * HDIM + n]);
    wrp[i] = *(uint32_t*)&h;
}

// ---------------------------------------------------------------------------
// SGEMM (fp32 SIMT, at FFMA roofline): hprime = (A@W)*inv; agg = hprime
// BM=128, BN=128, BK=16, 256 threads, 8x8 per thread
// ---------------------------------------------------------------------------
__global__ __launch_bounds__(256) void sgemm_fused_kernel(
    const float* __restrict__ A, const float* __restrict__ B,
    const float* __restrict__ inv,
    float* __restrict__ hprime, float* __restrict__ agg, int M)
{
    const int K = 256;
    __shared__ float As[16][128];   // transposed: As[k][m]
    __shared__ float Bs[16][128];

    const int block_row = blockIdx.x * 128;
    const int block_col = blockIdx.y * 128;
    const int tid = threadIdx.x;
    const int tr = tid >> 4;
    const int tc = tid & 15;

    const int a_row0 = tid >> 2;
    const int a_col  = (tid & 3) * 4;
    const int b_row0 = tid >> 5;
    const int b_col  = (tid & 31) * 4;

    float acc[8][8] = {};

    for (int k0 = 0; k0 < K; k0 += 16) {
        #pragma unroll
        for (int it = 0; it < 2; ++it) {
            int m = a_row0 + it * 64;
            int gr = block_row + m;
            float4 v = make_float4(0.f, 0.f, 0.f, 0.f);
            if (gr < M) v = *(const float4*)(A + (size_t)gr * K + k0 + a_col);
            As[a_col + 0][m] = v.x;
            As[a_col + 1][m] = v.y;
            As[a_col + 2][m] = v.z;
            As[a_col + 3][m] = v.w;
        }
        #pragma unroll
        for (int it = 0; it < 2; ++it) {
            int kk = b_row0 + it * 8;
            *(float4*)&Bs[kk][b_col] =
                *(const float4*)(B + (size_t)(k0 + kk) * 256 + block_col + b_col);
        }
        __syncthreads();

        #pragma unroll
        for (int kk = 0; kk < 16; ++kk) {
            float4 a0 = *(const float4*)&As[kk][tr * 8];
            float4 a1 = *(const float4*)&As[kk][tr * 8 + 4];
            float4 b0 = *(const float4*)&Bs[kk][tc * 8];
            float4 b1 = *(const float4*)&Bs[kk][tc * 8 + 4];
            float ar[8] = {a0.x, a0.y, a0.z, a0.w, a1.x, a1.y, a1.z, a1.w};
            float br[8] = {b0.x, b0.y, b0.z, b0.w, b1.x, b1.y, b1.z, b1.w};
            #pragma unroll
            for (int i = 0; i < 8; ++i)
                #pragma unroll
                for (int j = 0; j < 8; ++j)
                    acc[i][j] += ar[i] * br[j];
        }
        __syncthreads();
    }

    #pragma unroll
    for (int i = 0; i < 8; ++i) {
        int gr = block_row + tr * 8 + i;
        if (gr < M) {
            float iv = inv[gr];
            #pragma unroll
            for (int j = 0; j < 8; j += 4) {
                float4 o = make_float4(acc[i][j] * iv, acc[i][j+1] * iv,
                                       acc[i][j+2] * iv, acc[i][j+3] * iv);
                size_t off = (size_t)gr * 256 + block_col + tc * 8 + j;
                *(float4*)(hprime + off) = o;
                *(float4*)(agg    + off) = o;
            }
        }
    }
}

// ---------------------------------------------------------------------------
// Edge scatter: agg[dst,:] += hprime[src,:]   (pure vectorized reductions)
// ---------------------------------------------------------------------------
__global__ void scatter_kernel(const float* __restrict__ hp,
                               const int* __restrict__ src,
                               const int* __restrict__ dst,
                               float* __restrict__ agg, int e)
{
    int warp = (blockIdx.x * blockDim.x + threadIdx.x) >> 5;
    int lane = threadIdx.x & 31;
    if (warp >= e) return;
    int s = __ldg(&src[warp]);
    int d = __ldg(&dst[warp]);
    const float4* hpp = (const float4*)(hp + (size_t)s * 256);
    float* ap = agg + (size_t)d * 256;
    #pragma unroll
    for (int it = 0; it < 2; ++it) {
        int idx = lane + it * 32;
        float4 v = hpp[idx];
        asm volatile("red.global.add.v4.f32 [%0], {%1, %2, %3, %4};"
                     :: "l"(ap + (size_t)idx * 4),
                        "f"(v.x), "f"(v.y), "f"(v.z), "f"(v.w)
                     : "memory");
    }
}

// ---------------------------------------------------------------------------
// Epilogue: feat = agg * inv[row] + b, optional relu; optionally also write
// the half2 k-pair copy used by the ctx gather (layer 2 only).
// ---------------------------------------------------------------------------
template <bool RELU, bool WRITE_H>
__global__ void epilogue_kernel(const float* __restrict__ agg,
                                const float* __restrict__ inv,
                                const float* __restrict__ b,
                                float* __restrict__ feat,
                                uint32_t* __restrict__ feath, int total4)
{
    int t = blockIdx.x * blockDim.x + threadIdx.x;
    if (t >= total4) return;
    int row = t >> 6;
    int c4  = t & 63;
    float iv = inv[row];
    float4 v  = ((const float4*)agg)[t];
    float4 bb = ((const float4*)b)[c4];
    v.x = v.x * iv + bb.x; v.y = v.y * iv + bb.y;
    v.z = v.z * iv + bb.z; v.w = v.w * iv + bb.w;
    if (RELU) {
        v.x = fmaxf(v.x, 0.f); v.y = fmaxf(v.y, 0.f);
        v.z = fmaxf(v.z, 0.f); v.w = fmaxf(v.w, 0.f);
    }
    ((float4*)feat)[t] = v;
    if (WRITE_H) {
        __half2 h0 = __floats2half2_rn(v.x, v.y);
        __half2 h1 = __floats2half2_rn(v.z, v.w);
        uint2 packed = make_uint2(*(uint32_t*)&h0, *(uint32_t*)&h1);
        ((uint2*)feath)[t] = packed;
    }
}

// ---------------------------------------------------------------------------
// FP16 MMA
// ---------------------------------------------------------------------------
__device__ __forceinline__ void mma_f16(float d[4], const uint32_t a[4],
                                        const uint32_t b[2]) {
    asm volatile(
        "mma.sync.aligned.m16n8k16.row.col.f32.f16.f16.f32 "
        "{%0,%1,%2,%3}, {%4,%5,%6,%7}, {%8,%9}, {%0,%1,%2,%3};"
        : "+f"(d[0]), "+f"(d[1]), "+f"(d[2]), "+f"(d[3])
        : "r"(a[0]), "r"(a[1]), "r"(a[2]), "r"(a[3]),
          "r"(b[0]), "r"(b[1]));
}

// ---------------------------------------------------------------------------
// Context GEMM, FP16 tensor cores (m16n8k16). Operands pre-converted to
// half2 k-pairs (feath / wrp), so the hot loop has ZERO cvt instructions and
// the random A-gather moves half the bytes. Layout identical to R15
// (validated): A frag = 4x LDS.32, B frag = 1x LDS.64 via k-pair interleave.
//   out[row,c] = feat2[row,c] * ( sum_{j<len[row]} feat2[label[row,j],:]
//                                 @ Wr[j*256:, c]  + rb[c] )
// BM=128, BN=128, BK=32 (2 k-steps of 16), 8 warps (2x4), warp tile 64x32.
// Rows permuted longest-first (LPT) to kill the wave tail.
// ---------------------------------------------------------------------------
__global__ __launch_bounds__(256) void ctx_gemm_tc_kernel(
    const uint32_t* __restrict__ feath, // [M,128] half2 k-pairs
    const float* __restrict__ feat,     // [M,256] fp32 (final product)
    const int* __restrict__ perm,       // [M] rows sorted by clen desc
    const int* __restrict__ label,      // [M, 8]
    const int* __restrict__ clen,       // [M]
    const uint32_t* __restrict__ wrp,   // [1024,256] half2 k-pair rows of Wr
    const float* __restrict__ rb,       // [256]
    float* __restrict__ out, int M)
{
    __shared__ uint32_t As2[16][132];   // A k-pairs: As2[kp][m]
    __shared__ uint32_t Bsp[8][260];    // B k-pair interleave: [bprow][2n+kh]
    __shared__ int s_label[128][MAXCTX];
    __shared__ int s_len[128];
    __shared__ int s_row[128];
    __shared__ int s_maxlen;

    const int brow = blockIdx.x * 128;
    const int bcol = blockIdx.y * 128;
    const int tid  = threadIdx.x;
    const int lane = tid & 31;
    const int warp = tid >> 5;
    const int g    = lane >> 2;   // 0..7
    const int tig  = lane & 3;    // 0..3
    const int wm   = warp & 1;    // warp row (2)
    const int wn   = warp >> 1;   // warp col (4)

    // --- stage per-row metadata through the permutation ---
    if (tid < 128) {
        int gi = brow + tid;
        int row = (gi < M) ? perm[gi] : -1;
        s_row[tid] = row;
        s_len[tid] = (row >= 0) ? clen[row] : 0;
    }
    __syncthreads();
    for (int i = tid; i < 128 * MAXCTX; i += 256) {
        int r = i >> 3, j = i & 7;
        int row = s_row[r];
        s_label[r][j] = (row >= 0) ? label[(size_t)row * MAXCTX + j] : 0;
    }
    if (warp == 0) {
        int v = max(max(s_len[lane], s_len[lane + 32]),
                    max(s_len[lane + 64], s_len[lane + 96]));
        #pragma unroll
        for (int o = 16; o; o >>= 1) v = max(v, __shfl_xor_sync(0xffffffffu, v, o));
        if (lane == 0) s_maxlen = v;
    }
    __syncthreads();
    const int K_eff = s_maxlen * 256;   // bucketed: == len(bucket)*256

    float acc[4][4][4];
    #pragma unroll
    for (int i = 0; i < 4; ++i)
        #pragma unroll
        for (int j = 0; j < 4; ++j)
            #pragma unroll
            for (int c = 0; c < 4; ++c) acc[i][j][c] = 0.f;

    // A loader: thread covers row lm, 8 k-pairs at pair-base kpb
    const int lm  = tid >> 1;          // A row 0..127
    const int kpb = (tid & 1) * 8;     // k-pair base 0 / 8
    // B loader: thread covers k-pair bkp, 8 n at bnb
    const int bkp = tid & 15;          // k-pair 0..15
    const int bnb = (tid >> 4) * 8;    // n base 0..120

    uint4 rA[2], rB[2];

    auto loadTiles = [&](int k0) {
        const int j = k0 >> 8;              // context slot (constant in a tile)
        const int kp0 = ((k0 & 255) >> 1) + kpb;
        const int L = s_len[lm];
        if (j < L) {
            const uint32_t* abase = feath + (size_t)s_label[lm][j] * 128 + kp0;
            rA[0] = *(const uint4*)abase;
            rA[1] = *(const uint4*)(abase + 4);
        } else {
            rA[0] = rA[1] = make_uint4(0u, 0u, 0u, 0u);
        }
        const uint32_t* bbase = wrp + (size_t)((k0 >> 1) + bkp) * HDIM + bcol + bnb;
        rB[0] = *(const uint4*)bbase;
        rB[1] = *(const uint4*)(bbase + 4);
    };

    const int bprow = (bkp >> 3) * 4 + (bkp & 3);   // 0..7
    const int bkh   = (bkp >> 2) & 1;

    auto storeTiles = [&]() {
        // A: 8 k-pair words, pure copies
        As2[kpb + 0][lm] = rA[0].x;
        As2[kpb + 1][lm] = rA[0].y;
        As2[kpb + 2][lm] = rA[0].z;
        As2[kpb + 3][lm] = rA[0].w;
        As2[kpb + 4][lm] = rA[1].x;
        As2[kpb + 5][lm] = rA[1].y;
        As2[kpb + 6][lm] = rA[1].z;
        As2[kpb + 7][lm] = rA[1].w;
        // B: 8 n-values of k-pair bkp
        const uint32_t bv[8] = {rB[0].x, rB[0].y, rB[0].z, rB[0].w,
                                rB[1].x, rB[1].y, rB[1].z, rB[1].w};
        #pragma unroll
        for (int c = 0; c < 8; ++c)
            Bsp[bprow][2 * (bnb + c) + bkh] = bv[c];
    };

    if (K_eff > 0) {
        loadTiles(0);
        storeTiles();
        __syncthreads();

        for (int k0 = 0; k0 < K_eff; k0 += 32) {
            bool more = (k0 + 32) < K_eff;
            if (more) loadTiles(k0 + 32);   // global prefetch under the MMAs

            #pragma unroll
            for (int ks = 0; ks < 2; ++ks) {    // 2 k-steps of 16
                uint32_t af[4][4], bf[4][2];
                #pragma unroll
                for (int i = 0; i < 4; ++i) {
                    int mb = wm * 64 + i * 16 + g;
                    af[i][0] = As2[ks * 8 + tig    ][mb];
                    af[i][1] = As2[ks * 8 + tig    ][mb + 8];
                    af[i][2] = As2[ks * 8 + tig + 4][mb];
                    af[i][3] = As2[ks * 8 + tig + 4][mb + 8];
                }
                #pragma unroll
                for (int jn = 0; jn < 4; ++jn) {
                    int n = wn * 32 + jn * 8 + g;
                    uint2 bb = *(const uint2*)&Bsp[ks * 4 + tig][2 * n];
                    bf[jn][0] = bb.x;
                    bf[jn][1] = bb.y;
                }
                #pragma unroll
                for (int i = 0; i < 4; ++i)
                    #pragma unroll
                    for (int jn = 0; jn < 4; ++jn)
                        mma_f16(acc[i][jn], af[i], bf[jn]);
            }
            __syncthreads();
            if (more) { storeTiles(); __syncthreads(); }
        }
    }

    // fused epilogue through permutation: out[row] = feat2[row] * (acc + rb)
    #pragma unroll
    for (int i = 0; i < 4; ++i) {
        int lr0 = wm * 64 + i * 16 + g;
        int lr1 = lr0 + 8;
        int row0 = s_row[lr0];
        int row1 = s_row[lr1];
        #pragma unroll
        for (int jn = 0; jn < 4; ++jn) {
            int c = bcol + wn * 32 + jn * 8 + tig * 2;
            float2 bv = *(const float2*)(rb + c);
            if (row0 >= 0) {
                float2 fv = *(const float2*)(feat + (size_t)row0 * HDIM + c);
                float2 o;
                o.x = (acc[i][jn][0] + bv.x) * fv.x;
                o.y = (acc[i][jn][1] + bv.y) * fv.y;
                *(float2*)(out + (size_t)row0 * HDIM + c) = o;
            }
            if (row1 >= 0) {
                float2 fv = *(const float2*)(feat + (size_t)row1 * HDIM + c);
                float2 o;
                o.x = (acc[i][jn][2] + bv.x) * fv.x;
                o.y = (acc[i][jn][3] + bv.y) * fv.y;
                *(float2*)(out + (size_t)row1 * HDIM + c) = o;
            }
        }
    }
}

// ---------------------------------------------------------------------------
// Launch
// ---------------------------------------------------------------------------
extern "C" void kernel_launch(void* const* d_in, const int* in_sizes, int n_in,
                              void* d_out, int out_size)
{
    const float* x     = (const float*)d_in[0];
    const int*   ei    = (const int*)  d_in[1];   // [2, E]: src row then dst row
    const int*   label = (const int*)  d_in[2];
    const int*   clen  = (const int*)  d_in[3];
    const float* gW    = (const float*)d_in[4];
    const float* gb    = (const float*)d_in[5];
    const float* rW    = (const float*)d_in[6];
    const float* rb    = (const float*)d_in[7];
    float*       out   = (float*)d_out;

    const int N = in_sizes[3];
    const int E = in_sizes[1] / 2;
    const int* src = ei;
    const int* dst = ei + E;

    float *hp, *agg, *feat, *inv;
    uint32_t *feath, *wrp;
    int *perm;
    cudaGetSymbolAddress((void**)&hp,    g_h);
    cudaGetSymbolAddress((void**)&agg,   g_agg);
    cudaGetSymbolAddress((void**)&feat,  g_feat);
    cudaGetSymbolAddress((void**)&feath, g_feath);
    cudaGetSymbolAddress((void**)&wrp,   g_wrp);
    cudaGetSymbolAddress((void**)&inv,   g_inv);
    cudaGetSymbolAddress((void**)&perm,  g_perm);

    const int total4 = N * (HDIM / 4);
    const int TPB = 256;
    const int big = (E > N) ? E : N;
    dim3 gemm_grid((N + 127) / 128, 2);   // BN=128 -> 2 column blocks

    // --- normalization + length bucketing (fused setup) + Wr conversion ---
    setup_init_kernel<<<(N + TPB - 1) / TPB, TPB>>>(inv, N);
    setup_count_kernel<<<(big + TPB - 1) / TPB, TPB>>>(dst, inv, E, clen, N);
    setup_scan_kernel<<<(N + TPB - 1) / TPB, TPB>>>(inv, N);
    bucket_scatter_kernel<<<(N + TPB - 1) / TPB, TPB>>>(clen, N);
    wr_convert_kernel<<<(1024 * 256) / TPB, TPB>>>(rW, wrp);

    // --- GCN layer 1: feat1 = relu(inv*scatter(h') + b), h' = (x@W)*inv ---
    sgemm_fused_kernel<<<gemm_grid, TPB>>>(x, gW, inv, hp, agg, N);
    scatter_kernel<<<(E * 32 + TPB - 1) / TPB, TPB>>>(hp, src, dst, agg, E);
    epilogue_kernel<true, false><<<(total4 + TPB - 1) / TPB, TPB>>>(
        agg, inv, gb, feat, nullptr, total4);

    // --- GCN layer 2 (also emits half2 copy of feat2 for the ctx gather) ---
    sgemm_fused_kernel<<<gemm_grid, TPB>>>(feat, gW, inv, hp, agg, N);
    scatter_kernel<<<(E * 32 + TPB - 1) / TPB, TPB>>>(hp, src, dst, agg, E);
    epilogue_kernel<false, true><<<(total4 + TPB - 1) / TPB, TPB>>>(
        agg, inv, gb, feat, feath, total4);

    // --- bucketed (LPT-ordered) context gather-GEMM, fused final ---
    ctx_gemm_tc_kernel<<<gemm_grid, TPB>>>(feath, feat, perm, label, clen,
                                           wrp, rb, out, N);
}

// round 17
// speedup vs baseline: 1.6997x; 1.3007x over previous
#include <cuda_runtime.h>
#include <cuda_fp16.h>
#include <cstdint>

#define N_MAX   50000
#define HDIM    256
#define E_MAX   800000
#define MAXCTX  8

// ---------------------------------------------------------------------------
// Scratch (device globals -- no allocation allowed in kernel_launch)
// ---------------------------------------------------------------------------
__device__ float    g_h[N_MAX * HDIM];     // h' = (A @ W) * inv[row]
__device__ float    g_agg[N_MAX * HDIM];   // scatter accumulator
__device__ float    g_feat[N_MAX * HDIM];  // layer output (feat1 then feat2)
__device__ uint32_t g_feath[N_MAX * HDIM / 2];  // current A operand, half2 k-pairs
__device__ uint32_t g_wrp[(HDIM * MAXCTX / 2) * HDIM]; // Wr half2 k-pair rows
__device__ uint32_t g_wgp[(HDIM / 2) * HDIM];          // gW half2 k-pair rows
__device__ float    g_inv[N_MAX];          // deg, then rsqrt(deg)
__device__ int      g_bcnt[MAXCTX];        // bucket counts (clen in 0..7)
__device__ int      g_boff[MAXCTX];        // bucket offsets (mutated by scatter)
__device__ int      g_perm[N_MAX];         // rows sorted by context_len (desc)

// ---------------------------------------------------------------------------
// Fused setup kernels
// ---------------------------------------------------------------------------
__global__ void setup_init_kernel(float* deg, int n) {
    int i = blockIdx.x * blockDim.x + threadIdx.x;
    if (i < n) deg[i] = 1.0f;                       // self loop
    if (blockIdx.x == 0 && threadIdx.x < MAXCTX) g_bcnt[threadIdx.x] = 0;
}

__global__ void setup_count_kernel(const int* __restrict__ dst, float* deg, int e,
                                   const int* __restrict__ clen, int n) {
    int i = blockIdx.x * blockDim.x + threadIdx.x;
    if (i < e) atomicAdd(&deg[dst[i]], 1.0f);
    if (i < n) atomicAdd(&g_bcnt[clen[i]], 1);
}

__global__ void setup_scan_kernel(float* deg, int n) {
    int i = blockIdx.x * blockDim.x + threadIdx.x;
    if (i < n) deg[i] = rsqrtf(deg[i]);
    if (blockIdx.x == 0 && threadIdx.x == 0) {
        // DESCENDING length order (LPT): longest blocks scheduled first
        int acc = 0;
        for (int b = MAXCTX - 1; b >= 0; --b) { g_boff[b] = acc; acc += g_bcnt[b]; }
    }
}

__global__ void bucket_scatter_kernel(const int* __restrict__ clen, int n) {
    int i = blockIdx.x * blockDim.x + threadIdx.x;
    if (i < n) {
        int p = atomicAdd(&g_boff[clen[i]], 1);
        g_perm[p] = i;
    }
}

// One-shot conversion: W[2K,256] fp32 -> k-pair half2 rows
//   wp[kp*256 + n] = half2(W[2kp][n], W[2kp+1][n])      (grid sized by caller)
__global__ void w_convert_kernel(const float* __restrict__ W, uint32_t* __restrict__ wp) {
    int i = blockIdx.x * blockDim.x + threadIdx.x;
    int kp = i >> 8, n = i & 255;
    __half2 h = __floats2half2_rn(W[(2 * kp) * HDIM + n], W[(2 * kp + 1) * HDIM + n]);
    wp[i] = *(uint32_t*)&h;
}

// One-shot conversion: x[N,256] fp32 -> half2 k-pairs (consecutive pairs)
__global__ void x_convert_kernel(const float* __restrict__ x, uint32_t* __restrict__ xh,
                                 int total2) {
    int i = blockIdx.x * blockDim.x + threadIdx.x;
    if (i < total2) {
        float2 v = ((const float2*)x)[i];
        __half2 h = __floats2half2_rn(v.x, v.y);
        xh[i] = *(uint32_t*)&h;
    }
}

// ---------------------------------------------------------------------------
// FP16 MMA
// ---------------------------------------------------------------------------
__device__ __forceinline__ void mma_f16(float d[4], const uint32_t a[4],
                                        const uint32_t b[2]) {
    asm volatile(
        "mma.sync.aligned.m16n8k16.row.col.f32.f16.f16.f32 "
        "{%0,%1,%2,%3}, {%4,%5,%6,%7}, {%8,%9}, {%0,%1,%2,%3};"
        : "+f"(d[0]), "+f"(d[1]), "+f"(d[2]), "+f"(d[3])
        : "r"(a[0]), "r"(a[1]), "r"(a[2]), "r"(a[3]),
          "r"(b[0]), "r"(b[1]));
}

// ---------------------------------------------------------------------------
// GCN GEMM on FP16 tensor cores — the R16-proven ctx mainloop minus the
// gather. A (half2 k-pairs) is dense row-indexed; K=256 fixed (8 tiles).
//   hprime = (A @ W) * inv[row];  agg = hprime
// BM=128, BN=128, BK=32 (2 k-steps of 16), 8 warps (2x4), warp tile 64x32.
// ---------------------------------------------------------------------------
__global__ __launch_bounds__(256) void gcn_gemm_f16_kernel(
    const uint32_t* __restrict__ Ah,   // [M,128] half2 k-pairs
    const uint32_t* __restrict__ Wp,   // [128,256] half2 k-pair rows of gW
    const float* __restrict__ inv,
    float* __restrict__ hprime, float* __restrict__ agg, int M)
{
    __shared__ uint32_t As2[16][132];   // A k-pairs: As2[kp][m]
    __shared__ uint32_t Bsp[8][260];    // B k-pair interleave: [bprow][2n+kh]

    const int brow = blockIdx.x * 128;
    const int bcol = blockIdx.y * 128;
    const int tid  = threadIdx.x;
    const int lane = tid & 31;
    const int warp = tid >> 5;
    const int g    = lane >> 2;
    const int tig  = lane & 3;
    const int wm   = warp & 1;
    const int wn   = warp >> 1;

    float acc[4][4][4];
    #pragma unroll
    for (int i = 0; i < 4; ++i)
        #pragma unroll
        for (int j = 0; j < 4; ++j)
            #pragma unroll
            for (int c = 0; c < 4; ++c) acc[i][j][c] = 0.f;

    const int lm  = tid >> 1;          // A row 0..127
    const int kpb = (tid & 1) * 8;     // k-pair base 0 / 8
    const int bkp = tid & 15;          // B k-pair 0..15
    const int bnb = (tid >> 4) * 8;    // B n base

    uint4 rA[2], rB[2];

    auto loadTiles = [&](int k0) {
        const int row = brow + lm;
        if (row < M) {
            const uint32_t* abase = Ah + (size_t)row * 128 + (k0 >> 1) + kpb;
            rA[0] = *(const uint4*)abase;
            rA[1] = *(const uint4*)(abase + 4);
        } else {
            rA[0] = rA[1] = make_uint4(0u, 0u, 0u, 0u);
        }
        const uint32_t* bbase = Wp + (size_t)((k0 >> 1) + bkp) * HDIM + bcol + bnb;
        rB[0] = *(const uint4*)bbase;
        rB[1] = *(const uint4*)(bbase + 4);
    };

    const int bprow = (bkp >> 3) * 4 + (bkp & 3);
    const int bkh   = (bkp >> 2) & 1;

    auto storeTiles = [&]() {
        As2[kpb + 0][lm] = rA[0].x;
        As2[kpb + 1][lm] = rA[0].y;
        As2[kpb + 2][lm] = rA[0].z;
        As2[kpb + 3][lm] = rA[0].w;
        As2[kpb + 4][lm] = rA[1].x;
        As2[kpb + 5][lm] = rA[1].y;
        As2[kpb + 6][lm] = rA[1].z;
        As2[kpb + 7][lm] = rA[1].w;
        const uint32_t bv[8] = {rB[0].x, rB[0].y, rB[0].z, rB[0].w,
                                rB[1].x, rB[1].y, rB[1].z, rB[1].w};
        #pragma unroll
        for (int c = 0; c < 8; ++c)
            Bsp[bprow][2 * (bnb + c) + bkh] = bv[c];
    };

    loadTiles(0);
    storeTiles();
    __syncthreads();

    for (int k0 = 0; k0 < 256; k0 += 32) {
        bool more = (k0 + 32) < 256;
        if (more) loadTiles(k0 + 32);

        #pragma unroll
        for (int ks = 0; ks < 2; ++ks) {
            uint32_t af[4][4], bf[4][2];
            #pragma unroll
            for (int i = 0; i < 4; ++i) {
                int mb = wm * 64 + i * 16 + g;
                af[i][0] = As2[ks * 8 + tig    ][mb];
                af[i][1] = As2[ks * 8 + tig    ][mb + 8];
                af[i][2] = As2[ks * 8 + tig + 4][mb];
                af[i][3] = As2[ks * 8 + tig + 4][mb + 8];
            }
            #pragma unroll
            for (int jn = 0; jn < 4; ++jn) {
                int n = wn * 32 + jn * 8 + g;
                uint2 bb = *(const uint2*)&Bsp[ks * 4 + tig][2 * n];
                bf[jn][0] = bb.x;
                bf[jn][1] = bb.y;
            }
            #pragma unroll
            for (int i = 0; i < 4; ++i)
                #pragma unroll
                for (int jn = 0; jn < 4; ++jn)
                    mma_f16(acc[i][jn], af[i], bf[jn]);
        }
        __syncthreads();
        if (more) { storeTiles(); __syncthreads(); }
    }

    // epilogue: h' = acc * inv[row]; agg = h'
    #pragma unroll
    for (int i = 0; i < 4; ++i) {
        int r0 = brow + wm * 64 + i * 16 + g;
        int r1 = r0 + 8;
        float iv0 = (r0 < M) ? inv[r0] : 0.f;
        float iv1 = (r1 < M) ? inv[r1] : 0.f;
        #pragma unroll
        for (int jn = 0; jn < 4; ++jn) {
            int c = bcol + wn * 32 + jn * 8 + tig * 2;
            if (r0 < M) {
                float2 o = make_float2(acc[i][jn][0] * iv0, acc[i][jn][1] * iv0);
                *(float2*)(hprime + (size_t)r0 * HDIM + c) = o;
                *(float2*)(agg    + (size_t)r0 * HDIM + c) = o;
            }
            if (r1 < M) {
                float2 o = make_float2(acc[i][jn][2] * iv1, acc[i][jn][3] * iv1);
                *(float2*)(hprime + (size_t)r1 * HDIM + c) = o;
                *(float2*)(agg    + (size_t)r1 * HDIM + c) = o;
            }
        }
    }
}

// ---------------------------------------------------------------------------
// Edge scatter: agg[dst,:] += hprime[src,:]   (pure vectorized reductions)
// ---------------------------------------------------------------------------
__global__ void scatter_kernel(const float* __restrict__ hp,
                               const int* __restrict__ src,
                               const int* __restrict__ dst,
                               float* __restrict__ agg, int e)
{
    int warp = (blockIdx.x * blockDim.x + threadIdx.x) >> 5;
    int lane = threadIdx.x & 31;
    if (warp >= e) return;
    int s = __ldg(&src[warp]);
    int d = __ldg(&dst[warp]);
    const float4* hpp = (const float4*)(hp + (size_t)s * 256);
    float* ap = agg + (size_t)d * 256;
    #pragma unroll
    for (int it = 0; it < 2; ++it) {
        int idx = lane + it * 32;
        float4 v = hpp[idx];
        asm volatile("red.global.add.v4.f32 [%0], {%1, %2, %3, %4};"
                     :: "l"(ap + (size_t)idx * 4),
                        "f"(v.x), "f"(v.y), "f"(v.z), "f"(v.w)
                     : "memory");
    }
}

// ---------------------------------------------------------------------------
// Epilogue: feat = agg * inv[row] + b, optional relu; also write the half2
// k-pair copy used as the next GEMM's A operand.
// ---------------------------------------------------------------------------
template <bool RELU>
__global__ void epilogue_kernel(const float* __restrict__ agg,
                                const float* __restrict__ inv,
                                const float* __restrict__ b,
                                float* __restrict__ feat,
                                uint32_t* __restrict__ feath, int total4)
{
    int t = blockIdx.x * blockDim.x + threadIdx.x;
    if (t >= total4) return;
    int row = t >> 6;
    int c4  = t & 63;
    float iv = inv[row];
    float4 v  = ((const float4*)agg)[t];
    float4 bb = ((const float4*)b)[c4];
    v.x = v.x * iv + bb.x; v.y = v.y * iv + bb.y;
    v.z = v.z * iv + bb.z; v.w = v.w * iv + bb.w;
    if (RELU) {
        v.x = fmaxf(v.x, 0.f); v.y = fmaxf(v.y, 0.f);
        v.z = fmaxf(v.z, 0.f); v.w = fmaxf(v.w, 0.f);
    }
    ((float4*)feat)[t] = v;
    __half2 h0 = __floats2half2_rn(v.x, v.y);
    __half2 h1 = __floats2half2_rn(v.z, v.w);
    ((uint2*)feath)[t] = make_uint2(*(uint32_t*)&h0, *(uint32_t*)&h1);
}

// ---------------------------------------------------------------------------
// Context GEMM, FP16 tensor cores (R16-proven, 898us composite):
//   out[row,c] = feat2[row,c] * ( sum_{j<len[row]} feat2[label[row,j],:]
//                                 @ Wr[j*256:, c]  + rb[c] )
// BM=128, BN=128, BK=32, bucketed rows (LPT order), pre-converted operands.
// ---------------------------------------------------------------------------
__global__ __launch_bounds__(256) void ctx_gemm_tc_kernel(
    const uint32_t* __restrict__ feath, // [M,128] half2 k-pairs
    const float* __restrict__ feat,     // [M,256] fp32 (final product)
    const int* __restrict__ perm,       // [M] rows sorted by clen desc
    const int* __restrict__ label,      // [M, 8]
    const int* __restrict__ clen,       // [M]
    const uint32_t* __restrict__ wrp,   // [1024,256] half2 k-pair rows of Wr
    const float* __restrict__ rb,       // [256]
    float* __restrict__ out, int M)
{
    __shared__ uint32_t As2[16][132];
    __shared__ uint32_t Bsp[8][260];
    __shared__ int s_label[128][MAXCTX];
    __shared__ int s_len[128];
    __shared__ int s_row[128];
    __shared__ int s_maxlen;

    const int brow = blockIdx.x * 128;
    const int bcol = blockIdx.y * 128;
    const int tid  = threadIdx.x;
    const int lane = tid & 31;
    const int warp = tid >> 5;
    const int g    = lane >> 2;
    const int tig  = lane & 3;
    const int wm   = warp & 1;
    const int wn   = warp >> 1;

    if (tid < 128) {
        int gi = brow + tid;
        int row = (gi < M) ? perm[gi] : -1;
        s_row[tid] = row;
        s_len[tid] = (row >= 0) ? clen[row] : 0;
    }
    __syncthreads();
    for (int i = tid; i < 128 * MAXCTX; i += 256) {
        int r = i >> 3, j = i & 7;
        int row = s_row[r];
        s_label[r][j] = (row >= 0) ? label[(size_t)row * MAXCTX + j] : 0;
    }
    if (warp == 0) {
        int v = max(max(s_len[lane], s_len[lane + 32]),
                    max(s_len[lane + 64], s_len[lane + 96]));
        #pragma unroll
        for (int o = 16; o; o >>= 1) v = max(v, __shfl_xor_sync(0xffffffffu, v, o));
        if (lane == 0) s_maxlen = v;
    }
    __syncthreads();
    const int K_eff = s_maxlen * 256;

    float acc[4][4][4];
    #pragma unroll
    for (int i = 0; i < 4; ++i)
        #pragma unroll
        for (int j = 0; j < 4; ++j)
            #pragma unroll
            for (int c = 0; c < 4; ++c) acc[i][j][c] = 0.f;

    const int lm  = tid >> 1;
    const int kpb = (tid & 1) * 8;
    const int bkp = tid & 15;
    const int bnb = (tid >> 4) * 8;

    uint4 rA[2], rB[2];

    auto loadTiles = [&](int k0) {
        const int j = k0 >> 8;
        const int kp0 = ((k0 & 255) >> 1) + kpb;
        const int L = s_len[lm];
        if (j < L) {
            const uint32_t* abase = feath + (size_t)s_label[lm][j] * 128 + kp0;
            rA[0] = *(const uint4*)abase;
            rA[1] = *(const uint4*)(abase + 4);
        } else {
            rA[0] = rA[1] = make_uint4(0u, 0u, 0u, 0u);
        }
        const uint32_t* bbase = wrp + (size_t)((k0 >> 1) + bkp) * HDIM + bcol + bnb;
        rB[0] = *(const uint4*)bbase;
        rB[1] = *(const uint4*)(bbase + 4);
    };

    const int bprow = (bkp >> 3) * 4 + (bkp & 3);
    const int bkh   = (bkp >> 2) & 1;

    auto storeTiles = [&]() {
        As2[kpb + 0][lm] = rA[0].x;
        As2[kpb + 1][lm] = rA[0].y;
        As2[kpb + 2][lm] = rA[0].z;
        As2[kpb + 3][lm] = rA[0].w;
        As2[kpb + 4][lm] = rA[1].x;
        As2[kpb + 5][lm] = rA[1].y;
        As2[kpb + 6][lm] = rA[1].z;
        As2[kpb + 7][lm] = rA[1].w;
        const uint32_t bv[8] = {rB[0].x, rB[0].y, rB[0].z, rB[0].w,
                                rB[1].x, rB[1].y, rB[1].z, rB[1].w};
        #pragma unroll
        for (int c = 0; c < 8; ++c)
            Bsp[bprow][2 * (bnb + c) + bkh] = bv[c];
    };

    if (K_eff > 0) {
        loadTiles(0);
        storeTiles();
        __syncthreads();

        for (int k0 = 0; k0 < K_eff; k0 += 32) {
            bool more = (k0 + 32) < K_eff;
            if (more) loadTiles(k0 + 32);

            #pragma unroll
            for (int ks = 0; ks < 2; ++ks) {
                uint32_t af[4][4], bf[4][2];
                #pragma unroll
                for (int i = 0; i < 4; ++i) {
                    int mb = wm * 64 + i * 16 + g;
                    af[i][0] = As2[ks * 8 + tig    ][mb];
                    af[i][1] = As2[ks * 8 + tig    ][mb + 8];
                    af[i][2] = As2[ks * 8 + tig + 4][mb];
                    af[i][3] = As2[ks * 8 + tig + 4][mb + 8];
                }
                #pragma unroll
                for (int jn = 0; jn < 4; ++jn) {
                    int n = wn * 32 + jn * 8 + g;
                    uint2 bb = *(const uint2*)&Bsp[ks * 4 + tig][2 * n];
                    bf[jn][0] = bb.x;
                    bf[jn][1] = bb.y;
                }
                #pragma unroll
                for (int i = 0; i < 4; ++i)
                    #pragma unroll
                    for (int jn = 0; jn < 4; ++jn)
                        mma_f16(acc[i][jn], af[i], bf[jn]);
            }
            __syncthreads();
            if (more) { storeTiles(); __syncthreads(); }
        }
    }

    #pragma unroll
    for (int i = 0; i < 4; ++i) {
        int lr0 = wm * 64 + i * 16 + g;
        int lr1 = lr0 + 8;
        int row0 = s_row[lr0];
        int row1 = s_row[lr1];
        #pragma unroll
        for (int jn = 0; jn < 4; ++jn) {
            int c = bcol + wn * 32 + jn * 8 + tig * 2;
            float2 bv = *(const float2*)(rb + c);
            if (row0 >= 0) {
                float2 fv = *(const float2*)(feat + (size_t)row0 * HDIM + c);
                float2 o;
                o.x = (acc[i][jn][0] + bv.x) * fv.x;
                o.y = (acc[i][jn][1] + bv.y) * fv.y;
                *(float2*)(out + (size_t)row0 * HDIM + c) = o;
            }
            if (row1 >= 0) {
                float2 fv = *(const float2*)(feat + (size_t)row1 * HDIM + c);
                float2 o;
                o.x = (acc[i][jn][2] + bv.x) * fv.x;
                o.y = (acc[i][jn][3] + bv.y) * fv.y;
                *(float2*)(out + (size_t)row1 * HDIM + c) = o;
            }
        }
    }
}

// ---------------------------------------------------------------------------
// Launch
// ---------------------------------------------------------------------------
extern "C" void kernel_launch(void* const* d_in, const int* in_sizes, int n_in,
                              void* d_out, int out_size)
{
    const float* x     = (const float*)d_in[0];
    const int*   ei    = (const int*)  d_in[1];   // [2, E]: src row then dst row
    const int*   label = (const int*)  d_in[2];
    const int*   clen  = (const int*)  d_in[3];
    const float* gW    = (const float*)d_in[4];
    const float* gb    = (const float*)d_in[5];
    const float* rW    = (const float*)d_in[6];
    const float* rb    = (const float*)d_in[7];
    float*       out   = (float*)d_out;

    const int N = in_sizes[3];
    const int E = in_sizes[1] / 2;
    const int* src = ei;
    const int* dst = ei + E;

    float *hp, *agg, *feat, *inv;
    uint32_t *feath, *wrp, *wgp;
    int *perm;
    cudaGetSymbolAddress((void**)&hp,    g_h);
    cudaGetSymbolAddress((void**)&agg,   g_agg);
    cudaGetSymbolAddress((void**)&feat,  g_feat);
    cudaGetSymbolAddress((void**)&feath, g_feath);
    cudaGetSymbolAddress((void**)&wrp,   g_wrp);
    cudaGetSymbolAddress((void**)&wgp,   g_wgp);
    cudaGetSymbolAddress((void**)&inv,   g_inv);
    cudaGetSymbolAddress((void**)&perm,  g_perm);

    const int total4 = N * (HDIM / 4);
    const int total2 = N * (HDIM / 2);
    const int TPB = 256;
    const int big = (E > N) ? E : N;
    dim3 gemm_grid((N + 127) / 128, 2);   // BN=128 -> 2 column blocks

    // --- setup: normalization, bucketing, one-shot fp16 operand conversion ---
    setup_init_kernel<<<(N + TPB - 1) / TPB, TPB>>>(inv, N);
    setup_count_kernel<<<(big + TPB - 1) / TPB, TPB>>>(dst, inv, E, clen, N);
    setup_scan_kernel<<<(N + TPB - 1) / TPB, TPB>>>(inv, N);
    bucket_scatter_kernel<<<(N + TPB - 1) / TPB, TPB>>>(clen, N);
    w_convert_kernel<<<(1024 * 256) / TPB, TPB>>>(rW, wrp);   // Wr: 1024 k-pairs
    w_convert_kernel<<<(128 * 256) / TPB, TPB>>>(gW, wgp);    // gW: 128 k-pairs
    x_convert_kernel<<<(total2 + TPB - 1) / TPB, TPB>>>(x, feath, total2);

    // --- GCN layer 1: feat1 = relu(inv*scatter(h') + b), h' = (x@W)*inv ---
    gcn_gemm_f16_kernel<<<gemm_grid, TPB>>>(feath, wgp, inv, hp, agg, N);
    scatter_kernel<<<(E * 32 + TPB - 1) / TPB, TPB>>>(hp, src, dst, agg, E);
    epilogue_kernel<true><<<(total4 + TPB - 1) / TPB, TPB>>>(
        agg, inv, gb, feat, feath, total4);   // feath <- feat1 (half)

    // --- GCN layer 2 ---
    gcn_gemm_f16_kernel<<<gemm_grid, TPB>>>(feath, wgp, inv, hp, agg, N);
    scatter_kernel<<<(E * 32 + TPB - 1) / TPB, TPB>>>(hp, src, dst, agg, E);
    epilogue_kernel<false><<<(total4 + TPB - 1) / TPB, TPB>>>(
        agg, inv, gb, feat, feath, total4);   // feath <- feat2 (half)

    // --- bucketed (LPT) context gather-GEMM, fused final product ---
    ctx_gemm_tc_kernel<<<gemm_grid, TPB>>>(feath, feat, perm, label, clen,
                                           wrp, rb, out, N);
}